// round 1
// baseline (speedup 1.0000x reference)
#include <cuda_runtime.h>
#include <math.h>

#define BD 2
#define SD 2048
#define HDIM 1024
#define NHD 16
#define HDD 64
#define RD 64
#define MD (BD*SD)   /* 4096 */

static __device__ __forceinline__ float4 ldf4(const float* p) {
    return *reinterpret_cast<const float4*>(p);
}

// ---------------- scratch (device globals; no allocation allowed) ----------
__device__ float g_WqEff[HDIM*HDIM];
__device__ float g_WkEff[HDIM*HDIM];
__device__ float g_bqEff[HDIM];
__device__ float g_bkEff[HDIM];
__device__ float g_Qlow[(size_t)MD*HDIM];
__device__ float g_Klow[(size_t)MD*HDIM];
__device__ float g_V   [(size_t)MD*HDIM];
__device__ float g_ctx [(size_t)MD*HDIM];

// ---------------------------------------------------------------------------
// Effective low-rank weights: Weff[k][h*R+r] = sum_d W[k][h*HD+d] * Wl[d][r]
// beff[h*R+r] = sum_d b[h*HD+d] * Wl[d][r] + bl[r]
// grid: (HDIM/4, NHD), block: 256 = 4 k-rows x 64 r
// ---------------------------------------------------------------------------
__global__ void weff_kernel(const float* __restrict__ W,
                            const float* __restrict__ Wl,
                            const float* __restrict__ b,
                            const float* __restrict__ bl,
                            float* __restrict__ Weff,
                            float* __restrict__ beff) {
    __shared__ float Wls[HDD*RD];
    const int h  = blockIdx.y;
    const int r  = threadIdx.x & 63;
    const int kr = threadIdx.x >> 6;
    for (int i = threadIdx.x; i < HDD*RD; i += 256) Wls[i] = Wl[i];
    __syncthreads();
    const int k = blockIdx.x * 4 + kr;
    const float* wrow = W + (size_t)k*HDIM + h*HDD;
    float acc = 0.f;
    #pragma unroll
    for (int d = 0; d < HDD; d++) acc += wrow[d] * Wls[d*RD + r];
    Weff[(size_t)k*HDIM + h*RD + r] = acc;
    if (blockIdx.x == 0 && kr == 0) {
        float bacc = bl[r];
        #pragma unroll
        for (int d = 0; d < HDD; d++) bacc += b[h*HDD + d] * Wls[d*RD + r];
        beff[h*RD + r] = bacc;
    }
}

// ---------------------------------------------------------------------------
// C[M,N] = A[M,K] @ W[K,N] + bias[N]     (128x128x8 tiles, 8x8 per thread)
// ---------------------------------------------------------------------------
__global__ __launch_bounds__(256, 2)
void sgemm_bias(const float* __restrict__ A, const float* __restrict__ W,
                const float* __restrict__ bias, float* __restrict__ C,
                int Mdim, int Ndim, int Kdim) {
    constexpr int BM = 128, BN = 128, BK = 8;
    __shared__ float As[BK][BM];
    __shared__ float Bs[BK][BN];
    const int tid = threadIdx.x;
    const int blockRow = blockIdx.y, blockCol = blockIdx.x;
    const float* Ab = A + (size_t)blockRow * BM * Kdim;
    const float* Bb = W + blockCol * BN;

    float acc[8][8];
    #pragma unroll
    for (int i = 0; i < 8; i++)
        #pragma unroll
        for (int j = 0; j < 8; j++) acc[i][j] = 0.f;

    const int aRow = tid >> 1;          // 0..127
    const int aCol = (tid & 1) * 4;     // 0 or 4
    const int bRow = tid >> 5;          // 0..7
    const int bCol = (tid & 31) * 4;    // 0..124
    const int tRow = (tid >> 4) * 8;
    const int tCol = (tid & 15) * 8;

    for (int k0 = 0; k0 < Kdim; k0 += BK) {
        float4 av = ldf4(Ab + (size_t)aRow * Kdim + k0 + aCol);
        As[aCol + 0][aRow] = av.x;
        As[aCol + 1][aRow] = av.y;
        As[aCol + 2][aRow] = av.z;
        As[aCol + 3][aRow] = av.w;
        *reinterpret_cast<float4*>(&Bs[bRow][bCol]) =
            ldf4(Bb + (size_t)(k0 + bRow) * Ndim + bCol);
        __syncthreads();
        #pragma unroll
        for (int kk = 0; kk < BK; kk++) {
            float4 ra0 = *reinterpret_cast<const float4*>(&As[kk][tRow]);
            float4 ra1 = *reinterpret_cast<const float4*>(&As[kk][tRow + 4]);
            float4 rb0 = *reinterpret_cast<const float4*>(&Bs[kk][tCol]);
            float4 rb1 = *reinterpret_cast<const float4*>(&Bs[kk][tCol + 4]);
            float ra[8] = {ra0.x, ra0.y, ra0.z, ra0.w, ra1.x, ra1.y, ra1.z, ra1.w};
            float rb[8] = {rb0.x, rb0.y, rb0.z, rb0.w, rb1.x, rb1.y, rb1.z, rb1.w};
            #pragma unroll
            for (int i = 0; i < 8; i++)
                #pragma unroll
                for (int j = 0; j < 8; j++) acc[i][j] += ra[i] * rb[j];
        }
        __syncthreads();
    }
    #pragma unroll
    for (int i = 0; i < 8; i++) {
        const int row = blockRow * BM + tRow + i;
        #pragma unroll
        for (int j = 0; j < 8; j += 4) {
            const int col = blockCol * BN + tCol + j;
            float4 o;
            o.x = acc[i][j]     + bias[col];
            o.y = acc[i][j + 1] + bias[col + 1];
            o.z = acc[i][j + 2] + bias[col + 2];
            o.w = acc[i][j + 3] + bias[col + 3];
            *reinterpret_cast<float4*>(C + (size_t)row * Ndim + col) = o;
        }
    }
}

// ---------------------------------------------------------------------------
// Flash attention over (b, h, 64-query tile). R = HD = 64.
// block: 256 threads = 16x16, each owns 4x4 micro-tile.
// ---------------------------------------------------------------------------
static constexpr int AP = 72;                       // smem row pitch (floats)
static constexpr int ATTN_SMEM = 4 * 64 * AP * 4;   // Qs,Ks,Vs,Ps = 73728 B
static constexpr float SCALE = 0.125f;              // 1/sqrt(64)

__global__ __launch_bounds__(256)
void attn_kernel(const float* __restrict__ mask) {
    extern __shared__ float smf[];
    float* Qs = smf;
    float* Ks = Qs + 64 * AP;
    float* Vs = Ks + 64 * AP;
    float* Ps = Vs + 64 * AP;
    __shared__ float ms[64];

    const int b = blockIdx.z, h = blockIdx.y, qt = blockIdx.x;
    const int tid = threadIdx.x;
    const int tx = tid & 15, ty = tid >> 4;
    const size_t qbase = (size_t)b * SD + qt * 64;

    // load Q tile (natural layout Qs[q][r])
    for (int i = tid; i < 64 * 16; i += 256) {
        const int q = i >> 4, rc = (i & 15) * 4;
        *reinterpret_cast<float4*>(&Qs[q * AP + rc]) =
            ldf4(&g_Qlow[(qbase + q) * HDIM + h * 64 + rc]);
    }

    float m_[4], l_[4], O[4][4];
    #pragma unroll
    for (int i = 0; i < 4; i++) {
        m_[i] = -1e30f; l_[i] = 0.f;
        #pragma unroll
        for (int j = 0; j < 4; j++) O[i][j] = 0.f;
    }

    for (int kt = 0; kt < SD / 64; kt++) {
        __syncthreads();   // protects Ks/Vs/Ps from previous iteration readers
        const size_t kb = (size_t)b * SD + kt * 64;
        for (int i = tid; i < 64 * 16; i += 256) {
            const int k = i >> 4, rc = (i & 15) * 4;
            *reinterpret_cast<float4*>(&Ks[k * AP + rc]) =
                ldf4(&g_Klow[(kb + k) * HDIM + h * 64 + rc]);
            *reinterpret_cast<float4*>(&Vs[k * AP + rc]) =
                ldf4(&g_V[(kb + k) * HDIM + h * 64 + rc]);
        }
        if (tid < 64) ms[tid] = mask[(size_t)b * SD + kt * 64 + tid];
        __syncthreads();

        // scores: s[i][j] = sum_r Q[qi][r] * K[kj][r]
        float s[4][4];
        #pragma unroll
        for (int i = 0; i < 4; i++)
            #pragma unroll
            for (int j = 0; j < 4; j++) s[i][j] = 0.f;

        for (int r0 = 0; r0 < 64; r0 += 4) {
            float4 qv[4], kv[4];
            #pragma unroll
            for (int i = 0; i < 4; i++)
                qv[i] = *reinterpret_cast<const float4*>(&Qs[(ty * 4 + i) * AP + r0]);
            #pragma unroll
            for (int j = 0; j < 4; j++)
                kv[j] = *reinterpret_cast<const float4*>(&Ks[(tx * 4 + j) * AP + r0]);
            #pragma unroll
            for (int i = 0; i < 4; i++)
                #pragma unroll
                for (int j = 0; j < 4; j++)
                    s[i][j] += qv[i].x * kv[j].x + qv[i].y * kv[j].y +
                               qv[i].z * kv[j].z + qv[i].w * kv[j].w;
        }

        const float4 mj = *reinterpret_cast<const float4*>(&ms[tx * 4]);
        const float mvals[4] = {mj.x, mj.y, mj.z, mj.w};

        #pragma unroll
        for (int i = 0; i < 4; i++) {
            #pragma unroll
            for (int j = 0; j < 4; j++) s[i][j] = s[i][j] * SCALE + mvals[j];
            float rm = fmaxf(fmaxf(s[i][0], s[i][1]), fmaxf(s[i][2], s[i][3]));
            #pragma unroll
            for (int w = 8; w >= 1; w >>= 1)
                rm = fmaxf(rm, __shfl_xor_sync(0xffffffffu, rm, w));
            const float mn = fmaxf(m_[i], rm);
            float rs = 0.f;
            #pragma unroll
            for (int j = 0; j < 4; j++) { s[i][j] = __expf(s[i][j] - mn); rs += s[i][j]; }
            #pragma unroll
            for (int w = 8; w >= 1; w >>= 1)
                rs += __shfl_xor_sync(0xffffffffu, rs, w);
            const float f = __expf(m_[i] - mn);
            l_[i] = l_[i] * f + rs;
            m_[i] = mn;
            #pragma unroll
            for (int j = 0; j < 4; j++) O[i][j] *= f;
            *reinterpret_cast<float4*>(&Ps[(ty * 4 + i) * AP + tx * 4]) =
                make_float4(s[i][0], s[i][1], s[i][2], s[i][3]);
        }
        __syncthreads();

        // O += P @ V
        for (int k0 = 0; k0 < 64; k0 += 4) {
            float4 pv[4], vv[4];
            #pragma unroll
            for (int i = 0; i < 4; i++)
                pv[i] = *reinterpret_cast<const float4*>(&Ps[(ty * 4 + i) * AP + k0]);
            #pragma unroll
            for (int kk = 0; kk < 4; kk++)
                vv[kk] = *reinterpret_cast<const float4*>(&Vs[(k0 + kk) * AP + tx * 4]);
            const float* pf = reinterpret_cast<const float*>(pv);
            const float* vf = reinterpret_cast<const float*>(vv);
            #pragma unroll
            for (int i = 0; i < 4; i++)
                #pragma unroll
                for (int j = 0; j < 4; j++)
                    O[i][j] += pf[i*4+0]*vf[0*4+j] + pf[i*4+1]*vf[1*4+j] +
                               pf[i*4+2]*vf[2*4+j] + pf[i*4+3]*vf[3*4+j];
        }
    }

    #pragma unroll
    for (int i = 0; i < 4; i++) {
        const float inv = 1.f / l_[i];
        float4 o = make_float4(O[i][0]*inv, O[i][1]*inv, O[i][2]*inv, O[i][3]*inv);
        *reinterpret_cast<float4*>(
            &g_ctx[(qbase + ty * 4 + i) * HDIM + h * 64 + tx * 4]) = o;
    }
}

// ---------------------------------------------------------------------------
extern "C" void kernel_launch(void* const* d_in, const int* in_sizes, int n_in,
                              void* d_out, int out_size) {
    (void)in_sizes; (void)n_in; (void)out_size;
    const float* x    = (const float*)d_in[0];
    const float* mask = (const float*)d_in[1];
    const float* Wq   = (const float*)d_in[2];
    const float* bq   = (const float*)d_in[3];
    const float* Wk   = (const float*)d_in[4];
    const float* bk   = (const float*)d_in[5];
    const float* Wv   = (const float*)d_in[6];
    const float* bv   = (const float*)d_in[7];
    const float* Wql  = (const float*)d_in[8];
    const float* bql  = (const float*)d_in[9];
    const float* Wkl  = (const float*)d_in[10];
    const float* bkl  = (const float*)d_in[11];
    const float* Wo   = (const float*)d_in[12];
    const float* bo   = (const float*)d_in[13];
    float* out = (float*)d_out;

    float *pWqEff, *pWkEff, *pbqEff, *pbkEff, *pQ, *pK, *pV, *pCtx;
    cudaGetSymbolAddress((void**)&pWqEff, g_WqEff);
    cudaGetSymbolAddress((void**)&pWkEff, g_WkEff);
    cudaGetSymbolAddress((void**)&pbqEff, g_bqEff);
    cudaGetSymbolAddress((void**)&pbkEff, g_bkEff);
    cudaGetSymbolAddress((void**)&pQ,    g_Qlow);
    cudaGetSymbolAddress((void**)&pK,    g_Klow);
    cudaGetSymbolAddress((void**)&pV,    g_V);
    cudaGetSymbolAddress((void**)&pCtx,  g_ctx);

    cudaFuncSetAttribute(attn_kernel,
                         cudaFuncAttributeMaxDynamicSharedMemorySize, ATTN_SMEM);

    // effective low-rank weights (folds q@Wql / k@Wkl into the projections)
    weff_kernel<<<dim3(HDIM / 4, NHD), 256>>>(Wq, Wql, bq, bql, pWqEff, pbqEff);
    weff_kernel<<<dim3(HDIM / 4, NHD), 256>>>(Wk, Wkl, bk, bkl, pWkEff, pbkEff);

    const dim3 gg(HDIM / 128, MD / 128);
    sgemm_bias<<<gg, 256>>>(x, pWqEff, pbqEff, pQ, MD, HDIM, HDIM);
    sgemm_bias<<<gg, 256>>>(x, pWkEff, pbkEff, pK, MD, HDIM, HDIM);
    sgemm_bias<<<gg, 256>>>(x, Wv, bv, pV, MD, HDIM, HDIM);

    attn_kernel<<<dim3(SD / 64, NHD, BD), 256, ATTN_SMEM>>>(mask);

    sgemm_bias<<<gg, 256>>>(pCtx, Wo, bo, out, MD, HDIM, HDIM);
}

// round 4
// speedup vs baseline: 1.4807x; 1.4807x over previous
#include <cuda_runtime.h>
#include <math.h>

#define BD 2
#define SD 2048
#define HDIM 1024
#define NHD 16
#define HDD 64
#define RD 64
#define MD (BD*SD)   /* 4096 */

typedef unsigned long long ull;

static __device__ __forceinline__ float4 ldf4(const float* p) {
    return *reinterpret_cast<const float4*>(p);
}
static __device__ __forceinline__ ull pk2(float lo, float hi) {
    ull r; asm("mov.b64 %0, {%1, %2};" : "=l"(r) : "f"(lo), "f"(hi)); return r;
}
static __device__ __forceinline__ ull bc2(float a) {
    ull r; asm("mov.b64 %0, {%1, %1};" : "=l"(r) : "f"(a)); return r;
}
static __device__ __forceinline__ void fma2(ull& d, ull a, ull b) {
    asm("fma.rn.f32x2 %0, %1, %2, %0;" : "+l"(d) : "l"(a), "l"(b));
}
static __device__ __forceinline__ void mul2(ull& d, ull a) {
    asm("mul.rn.f32x2 %0, %0, %1;" : "+l"(d) : "l"(a));
}
static __device__ __forceinline__ float2 up2(ull v) {
    float2 r; asm("mov.b64 {%0, %1}, %2;" : "=f"(r.x), "=f"(r.y) : "l"(v)); return r;
}

// ---------------- scratch (device globals; no allocation allowed) ----------
__device__ float g_WqEff[HDIM*HDIM];
__device__ float g_WkEff[HDIM*HDIM];
__device__ float g_bqEff[HDIM];
__device__ float g_bkEff[HDIM];
__device__ float g_Qlow[(size_t)MD*HDIM];
__device__ float g_Klow[(size_t)MD*HDIM];
__device__ float g_V   [(size_t)MD*HDIM];
__device__ float g_ctx [(size_t)MD*HDIM];

// ---------------------------------------------------------------------------
// Effective low-rank weights: Weff[k][h*R+r] = sum_d W[k][h*HD+d] * Wl[d][r]
// ---------------------------------------------------------------------------
__global__ void weff_kernel(const float* __restrict__ W,
                            const float* __restrict__ Wl,
                            const float* __restrict__ b,
                            const float* __restrict__ bl,
                            float* __restrict__ Weff,
                            float* __restrict__ beff) {
    __shared__ float Wls[HDD*RD];
    const int h  = blockIdx.y;
    const int r  = threadIdx.x & 63;
    const int kr = threadIdx.x >> 6;
    for (int i = threadIdx.x; i < HDD*RD; i += 256) Wls[i] = Wl[i];
    __syncthreads();
    const int k = blockIdx.x * 4 + kr;
    const float* wrow = W + (size_t)k*HDIM + h*HDD;
    float acc = 0.f;
    #pragma unroll
    for (int d = 0; d < HDD; d++) acc += wrow[d] * Wls[d*RD + r];
    Weff[(size_t)k*HDIM + h*RD + r] = acc;
    if (blockIdx.x == 0 && kr == 0) {
        float bacc = bl[r];
        #pragma unroll
        for (int d = 0; d < HDD; d++) bacc += b[h*HDD + d] * Wls[d*RD + r];
        beff[h*RD + r] = bacc;
    }
}

// ---------------------------------------------------------------------------
// C[M,N] = A[M,K] @ W[K,N] + bias[N]   (128x128x8 tiles, 8x8/thread, FFMA2)
// ---------------------------------------------------------------------------
__global__ __launch_bounds__(256, 2)
void sgemm_bias(const float* __restrict__ A, const float* __restrict__ W,
                const float* __restrict__ bias, float* __restrict__ C,
                int Mdim, int Ndim, int Kdim) {
    constexpr int BM = 128, BN = 128, BK = 8;
    __shared__ float As[BK][BM];
    __shared__ float Bs[BK][BN];
    const int tid = threadIdx.x;
    const int blockRow = blockIdx.y, blockCol = blockIdx.x;
    const float* Ab = A + (size_t)blockRow * BM * Kdim;
    const float* Bb = W + blockCol * BN;

    ull acc2[8][4];
    #pragma unroll
    for (int i = 0; i < 8; i++)
        #pragma unroll
        for (int j = 0; j < 4; j++) acc2[i][j] = 0ULL;

    const int aRow = tid >> 1;
    const int aCol = (tid & 1) * 4;
    const int bRow = tid >> 5;
    const int bCol = (tid & 31) * 4;
    const int tRow = (tid >> 4) * 8;
    const int tCol = (tid & 15) * 8;

    for (int k0 = 0; k0 < Kdim; k0 += BK) {
        float4 av = ldf4(Ab + (size_t)aRow * Kdim + k0 + aCol);
        As[aCol + 0][aRow] = av.x;
        As[aCol + 1][aRow] = av.y;
        As[aCol + 2][aRow] = av.z;
        As[aCol + 3][aRow] = av.w;
        *reinterpret_cast<float4*>(&Bs[bRow][bCol]) =
            ldf4(Bb + (size_t)(k0 + bRow) * Ndim + bCol);
        __syncthreads();
        #pragma unroll
        for (int kk = 0; kk < BK; kk++) {
            float4 ra0 = *reinterpret_cast<const float4*>(&As[kk][tRow]);
            float4 ra1 = *reinterpret_cast<const float4*>(&As[kk][tRow + 4]);
            float4 rb0 = *reinterpret_cast<const float4*>(&Bs[kk][tCol]);
            float4 rb1 = *reinterpret_cast<const float4*>(&Bs[kk][tCol + 4]);
            ull rbp[4] = {pk2(rb0.x, rb0.y), pk2(rb0.z, rb0.w),
                          pk2(rb1.x, rb1.y), pk2(rb1.z, rb1.w)};
            float ra[8] = {ra0.x, ra0.y, ra0.z, ra0.w, ra1.x, ra1.y, ra1.z, ra1.w};
            #pragma unroll
            for (int i = 0; i < 8; i++) {
                ull avp = bc2(ra[i]);
                #pragma unroll
                for (int jp = 0; jp < 4; jp++) fma2(acc2[i][jp], avp, rbp[jp]);
            }
        }
        __syncthreads();
    }
    #pragma unroll
    for (int i = 0; i < 8; i++) {
        const int row = blockRow * BM + tRow + i;
        #pragma unroll
        for (int jp = 0; jp < 4; jp += 2) {
            const int col = blockCol * BN + tCol + jp * 2;
            float2 v0 = up2(acc2[i][jp]);
            float2 v1 = up2(acc2[i][jp + 1]);
            float4 o;
            o.x = v0.x + bias[col];
            o.y = v0.y + bias[col + 1];
            o.z = v1.x + bias[col + 2];
            o.w = v1.y + bias[col + 3];
            *reinterpret_cast<float4*>(C + (size_t)row * Ndim + col) = o;
        }
    }
}

// ---------------------------------------------------------------------------
// Flash attention: 64 queries x 128 keys per iter, 256 threads, FFMA2.
// tx (0..15): 8 key cols in scores, 4 out dims in PV. ty (0..15): 4 queries.
// ---------------------------------------------------------------------------
static constexpr int QP = 68;    // Qt pitch (Qt[r][q], r<64, q<64)
static constexpr int KP = 132;   // Kt pitch (Kt[r][k], r<64, k<128)
static constexpr int VP = 68;    // V  pitch (V[k][d],  k<128, d<64)
static constexpr int PP = 68;    // Pt pitch (Pt[k][i], k<128, i<64)
static constexpr int ATTN_FLOATS = 64*QP + 64*KP + 128*VP + 128*PP + 128;
static constexpr int ATTN_SMEM = ATTN_FLOATS * 4;
static constexpr float SCALE = 0.125f;

__global__ __launch_bounds__(256)
void attn_kernel(const float* __restrict__ mask) {
    extern __shared__ float smf[];
    float* Qt = smf;
    float* Kt = Qt + 64 * QP;
    float* Vs = Kt + 64 * KP;
    float* Pt = Vs + 128 * VP;
    float* ms = Pt + 128 * PP;

    const int b = blockIdx.z, h = blockIdx.y, qt = blockIdx.x;
    const int tid = threadIdx.x;
    const int tx = tid & 15, ty = tid >> 4;
    const int i0 = ty * 4;          // query offset
    const int d0 = tx * 4;          // output dim offset
    const int j0 = tx * 8;          // key-col offset in scores
    const size_t qbase = (size_t)b * SD + qt * 64;

    // load Q tile transposed: Qt[r][q]
    for (int idx = tid; idx < 64 * 16; idx += 256) {
        const int q = idx >> 4, rc = (idx & 15) * 4;
        float4 v = ldf4(&g_Qlow[(qbase + q) * HDIM + h * 64 + rc]);
        Qt[(rc + 0) * QP + q] = v.x;
        Qt[(rc + 1) * QP + q] = v.y;
        Qt[(rc + 2) * QP + q] = v.z;
        Qt[(rc + 3) * QP + q] = v.w;
    }

    float m_[4], l_[4];
    ull O2[4][2];
    #pragma unroll
    for (int i = 0; i < 4; i++) {
        m_[i] = -1e30f; l_[i] = 0.f;
        O2[i][0] = 0ULL; O2[i][1] = 0ULL;
    }

    for (int kt = 0; kt < SD / 128; kt++) {
        __syncthreads();      // protect Kt/Vs/Pt from previous iteration
        const size_t kb = (size_t)b * SD + kt * 128;
        for (int idx = tid; idx < 128 * 16; idx += 256) {
            const int k = idx >> 4, rc = (idx & 15) * 4;
            float4 v = ldf4(&g_Klow[(kb + k) * HDIM + h * 64 + rc]);
            Kt[(rc + 0) * KP + k] = v.x;
            Kt[(rc + 1) * KP + k] = v.y;
            Kt[(rc + 2) * KP + k] = v.z;
            Kt[(rc + 3) * KP + k] = v.w;
            *reinterpret_cast<float4*>(&Vs[k * VP + rc]) =
                ldf4(&g_V[(kb + k) * HDIM + h * 64 + rc]);
        }
        if (tid < 128) ms[tid] = mask[(size_t)b * SD + kt * 128 + tid];
        __syncthreads();

        // ---- scores: s[i][j] = sum_r Qt[r][i0+i] * Kt[r][j0+j] -------------
        ull s2[4][4];
        #pragma unroll
        for (int i = 0; i < 4; i++)
            #pragma unroll
            for (int jp = 0; jp < 4; jp++) s2[i][jp] = 0ULL;

        #pragma unroll 4
        for (int r = 0; r < 64; r++) {
            float4 qv = *reinterpret_cast<const float4*>(&Qt[r * QP + i0]);
            ulonglong2 ka = *reinterpret_cast<const ulonglong2*>(&Kt[r * KP + j0]);
            ulonglong2 kb2 = *reinterpret_cast<const ulonglong2*>(&Kt[r * KP + j0 + 4]);
            const ull kp[4] = {ka.x, ka.y, kb2.x, kb2.y};
            const float qs[4] = {qv.x, qv.y, qv.z, qv.w};
            #pragma unroll
            for (int i = 0; i < 4; i++) {
                ull qb = bc2(qs[i]);
                #pragma unroll
                for (int jp = 0; jp < 4; jp++) fma2(s2[i][jp], qb, kp[jp]);
            }
        }

        float s[4][8];
        #pragma unroll
        for (int i = 0; i < 4; i++)
            #pragma unroll
            for (int jp = 0; jp < 4; jp++) {
                float2 t = up2(s2[i][jp]);
                s[i][2*jp] = t.x; s[i][2*jp+1] = t.y;
            }

        float4 mr0 = *reinterpret_cast<const float4*>(&ms[j0]);
        float4 mr1 = *reinterpret_cast<const float4*>(&ms[j0 + 4]);
        const float mv[8] = {mr0.x, mr0.y, mr0.z, mr0.w, mr1.x, mr1.y, mr1.z, mr1.w};

        #pragma unroll
        for (int i = 0; i < 4; i++) {
            #pragma unroll
            for (int j = 0; j < 8; j++) s[i][j] = s[i][j] * SCALE + mv[j];
            float rm = s[i][0];
            #pragma unroll
            for (int j = 1; j < 8; j++) rm = fmaxf(rm, s[i][j]);
            #pragma unroll
            for (int w = 8; w >= 1; w >>= 1)
                rm = fmaxf(rm, __shfl_xor_sync(0xffffffffu, rm, w));
            const float mn = fmaxf(m_[i], rm);
            float rs = 0.f;
            #pragma unroll
            for (int j = 0; j < 8; j++) { s[i][j] = __expf(s[i][j] - mn); rs += s[i][j]; }
            #pragma unroll
            for (int w = 8; w >= 1; w >>= 1)
                rs += __shfl_xor_sync(0xffffffffu, rs, w);
            const float f = __expf(m_[i] - mn);
            l_[i] = l_[i] * f + rs;
            m_[i] = mn;
            ull fb = bc2(f);
            mul2(O2[i][0], fb);
            mul2(O2[i][1], fb);
        }

        // store P transposed: Pt[k][i]
        #pragma unroll
        for (int jj = 0; jj < 8; jj++) {
            float4 col = make_float4(s[0][jj], s[1][jj], s[2][jj], s[3][jj]);
            *reinterpret_cast<float4*>(&Pt[(j0 + jj) * PP + i0]) = col;
        }
        __syncthreads();

        // ---- O += P @ V ----------------------------------------------------
        #pragma unroll 4
        for (int k = 0; k < 128; k++) {
            float4 pv = *reinterpret_cast<const float4*>(&Pt[k * PP + i0]);
            ulonglong2 vv = *reinterpret_cast<const ulonglong2*>(&Vs[k * VP + d0]);
            const float ps[4] = {pv.x, pv.y, pv.z, pv.w};
            #pragma unroll
            for (int i = 0; i < 4; i++) {
                ull pb = bc2(ps[i]);
                fma2(O2[i][0], pb, vv.x);
                fma2(O2[i][1], pb, vv.y);
            }
        }
    }

    #pragma unroll
    for (int i = 0; i < 4; i++) {
        const float inv = 1.f / l_[i];
        float2 a = up2(O2[i][0]);
        float2 c = up2(O2[i][1]);
        float4 o = make_float4(a.x * inv, a.y * inv, c.x * inv, c.y * inv);
        *reinterpret_cast<float4*>(
            &g_ctx[(qbase + i0 + i) * HDIM + h * 64 + d0]) = o;
    }
}

// ---------------------------------------------------------------------------
extern "C" void kernel_launch(void* const* d_in, const int* in_sizes, int n_in,
                              void* d_out, int out_size) {
    (void)in_sizes; (void)n_in; (void)out_size;
    const float* x    = (const float*)d_in[0];
    const float* mask = (const float*)d_in[1];
    const float* Wq   = (const float*)d_in[2];
    const float* bq   = (const float*)d_in[3];
    const float* Wk   = (const float*)d_in[4];
    const float* bk   = (const float*)d_in[5];
    const float* Wv   = (const float*)d_in[6];
    const float* bv   = (const float*)d_in[7];
    const float* Wql  = (const float*)d_in[8];
    const float* bql  = (const float*)d_in[9];
    const float* Wkl  = (const float*)d_in[10];
    const float* bkl  = (const float*)d_in[11];
    const float* Wo   = (const float*)d_in[12];
    const float* bo   = (const float*)d_in[13];
    float* out = (float*)d_out;

    float *pWqEff, *pWkEff, *pbqEff, *pbkEff, *pQ, *pK, *pV, *pCtx;
    cudaGetSymbolAddress((void**)&pWqEff, g_WqEff);
    cudaGetSymbolAddress((void**)&pWkEff, g_WkEff);
    cudaGetSymbolAddress((void**)&pbqEff, g_bqEff);
    cudaGetSymbolAddress((void**)&pbkEff, g_bkEff);
    cudaGetSymbolAddress((void**)&pQ,    g_Qlow);
    cudaGetSymbolAddress((void**)&pK,    g_Klow);
    cudaGetSymbolAddress((void**)&pV,    g_V);
    cudaGetSymbolAddress((void**)&pCtx,  g_ctx);

    cudaFuncSetAttribute(attn_kernel,
                         cudaFuncAttributeMaxDynamicSharedMemorySize, ATTN_SMEM);

    weff_kernel<<<dim3(HDIM / 4, NHD), 256>>>(Wq, Wql, bq, bql, pWqEff, pbqEff);
    weff_kernel<<<dim3(HDIM / 4, NHD), 256>>>(Wk, Wkl, bk, bkl, pWkEff, pbkEff);

    const dim3 gg(HDIM / 128, MD / 128);
    sgemm_bias<<<gg, 256>>>(x, pWqEff, pbqEff, pQ, MD, HDIM, HDIM);
    sgemm_bias<<<gg, 256>>>(x, pWkEff, pbkEff, pK, MD, HDIM, HDIM);
    sgemm_bias<<<gg, 256>>>(x, Wv, bv, pV, MD, HDIM, HDIM);

    attn_kernel<<<dim3(SD / 64, NHD, BD), 256, ATTN_SMEM>>>(mask);

    sgemm_bias<<<gg, 256>>>(pCtx, Wo, bo, out, MD, HDIM, HDIM);
}

// round 10
// speedup vs baseline: 1.9449x; 1.3135x over previous
#include <cuda_runtime.h>
#include <math.h>
#include <stdint.h>

#define BD 2
#define SD 2048
#define HDIM 1024
#define NHD 16
#define HDD 64
#define RD 64
#define MD (BD*SD)   /* 4096 */

typedef unsigned long long ull;

static __device__ __forceinline__ float4 ldf4(const float* p) {
    return *reinterpret_cast<const float4*>(p);
}
static __device__ __forceinline__ ull pk2(float lo, float hi) {
    ull r; asm("mov.b64 %0, {%1, %2};" : "=l"(r) : "f"(lo), "f"(hi)); return r;
}
static __device__ __forceinline__ ull bc2(float a) {
    ull r; asm("mov.b64 %0, {%1, %1};" : "=l"(r) : "f"(a)); return r;
}
static __device__ __forceinline__ void fma2(ull& d, ull a, ull b) {
    asm("fma.rn.f32x2 %0, %1, %2, %0;" : "+l"(d) : "l"(a), "l"(b));
}
static __device__ __forceinline__ void mul2(ull& d, ull a) {
    asm("mul.rn.f32x2 %0, %0, %1;" : "+l"(d) : "l"(a));
}
static __device__ __forceinline__ float2 up2(ull v) {
    float2 r; asm("mov.b64 {%0, %1}, %2;" : "=f"(r.x), "=f"(r.y) : "l"(v)); return r;
}
static __device__ __forceinline__ uint32_t cvt_tf32(float v) {
    uint32_t r; asm("cvt.rna.tf32.f32 %0, %1;" : "=r"(r) : "f"(v)); return r;
}
// m16n8k8 tf32 mma (sm_80+ PTX -> valid on compute_103 without the 'a' suffix)
static __device__ __forceinline__ void mma_tf32(float* d, const uint32_t* a,
                                                const uint32_t* b) {
    asm volatile(
        "mma.sync.aligned.m16n8k8.row.col.f32.tf32.tf32.f32 "
        "{%0,%1,%2,%3}, {%4,%5,%6,%7}, {%8,%9}, {%0,%1,%2,%3};"
        : "+f"(d[0]), "+f"(d[1]), "+f"(d[2]), "+f"(d[3])
        : "r"(a[0]), "r"(a[1]), "r"(a[2]), "r"(a[3]), "r"(b[0]), "r"(b[1]));
}

// ---------------- scratch (device globals; no allocation allowed) ----------
__device__ float g_WqEff[HDIM*HDIM];
__device__ float g_WkEff[HDIM*HDIM];
__device__ float g_bqEff[HDIM];
__device__ float g_bkEff[HDIM];
__device__ float g_Qlow[(size_t)MD*HDIM];
__device__ float g_Klow[(size_t)MD*HDIM];
__device__ float g_V   [(size_t)MD*HDIM];
__device__ float g_ctx [(size_t)MD*HDIM];

// ---------------------------------------------------------------------------
// Effective low-rank weights
// ---------------------------------------------------------------------------
__global__ void weff_kernel(const float* __restrict__ W,
                            const float* __restrict__ Wl,
                            const float* __restrict__ b,
                            const float* __restrict__ bl,
                            float* __restrict__ Weff,
                            float* __restrict__ beff) {
    __shared__ float Wls[HDD*RD];
    const int h  = blockIdx.y;
    const int r  = threadIdx.x & 63;
    const int kr = threadIdx.x >> 6;
    for (int i = threadIdx.x; i < HDD*RD; i += 256) Wls[i] = Wl[i];
    __syncthreads();
    const int k = blockIdx.x * 4 + kr;
    const float* wrow = W + (size_t)k*HDIM + h*HDD;
    float acc = 0.f;
    #pragma unroll
    for (int d = 0; d < HDD; d++) acc += wrow[d] * Wls[d*RD + r];
    Weff[(size_t)k*HDIM + h*RD + r] = acc;
    if (blockIdx.x == 0 && kr == 0) {
        float bacc = bl[r];
        #pragma unroll
        for (int d = 0; d < HDD; d++) bacc += b[h*HDD + d] * Wls[d*RD + r];
        beff[h*RD + r] = bacc;
    }
}

// ---------------------------------------------------------------------------
// mma.sync tf32 GEMM: C[4096,1024] = A @ W + bias.
// CTA 128x128, BK=32, 8 warps in 4(m) x 2(n); warp tile 32x64 (2x8 mma tiles).
// As[m][k] pitch 36 -> frag-load bank == lane (conflict-free).
// Bs[k][n] pitch 132 -> frag-load bank == 4k+n (bijective, conflict-free).
// ---------------------------------------------------------------------------
static constexpr int APM = 36;    // A smem pitch (k-extent 32 + 4)
static constexpr int BPN = 132;   // B smem pitch (n-extent 128 + 4)

__global__ __launch_bounds__(256, 2)
void mma_gemm_bias(const float* __restrict__ A, const float* __restrict__ W,
                   const float* __restrict__ bias, float* __restrict__ C) {
    __shared__ uint32_t As[128 * APM];   // 18.0 KB
    __shared__ uint32_t Bs[32 * BPN];    // 16.5 KB

    const int tid = threadIdx.x;
    const int wid = tid >> 5, lane = tid & 31;
    const int lr = lane >> 2, lc = lane & 3;
    const int warp_m = wid & 3, warp_n = wid >> 2;
    const int m0 = blockIdx.y * 128, n0 = blockIdx.x * 128;

    float acc[2][8][4];
    #pragma unroll
    for (int mt = 0; mt < 2; mt++)
        #pragma unroll
        for (int nt = 0; nt < 8; nt++)
            #pragma unroll
            for (int e = 0; e < 4; e++) acc[mt][nt][e] = 0.f;

    for (int k0 = 0; k0 < HDIM; k0 += 32) {
        // stage A (128 rows x 32 k) and B (32 k x 128 n), cvt -> tf32
        #pragma unroll
        for (int it = 0; it < 4; it++) {
            const int idx = it * 256 + tid;
            const int m = idx >> 3, k4 = idx & 7;
            float4 v = ldf4(A + (size_t)(m0 + m) * HDIM + k0 + k4 * 4);
            uint4 t = make_uint4(cvt_tf32(v.x), cvt_tf32(v.y),
                                 cvt_tf32(v.z), cvt_tf32(v.w));
            *reinterpret_cast<uint4*>(&As[m * APM + k4 * 4]) = t;
        }
        #pragma unroll
        for (int it = 0; it < 4; it++) {
            const int idx = it * 256 + tid;
            const int kr = idx >> 5, n4 = idx & 31;
            float4 v = ldf4(W + (size_t)(k0 + kr) * HDIM + n0 + n4 * 4);
            uint4 t = make_uint4(cvt_tf32(v.x), cvt_tf32(v.y),
                                 cvt_tf32(v.z), cvt_tf32(v.w));
            *reinterpret_cast<uint4*>(&Bs[kr * BPN + n4 * 4]) = t;
        }
        __syncthreads();

        #pragma unroll
        for (int ks = 0; ks < 4; ks++) {
            const int kb = ks * 8;
            uint32_t af[2][4], bf[8][2];
            #pragma unroll
            for (int mt = 0; mt < 2; mt++) {
                const int rbase = (warp_m * 32 + mt * 16 + lr) * APM;
                af[mt][0] = As[rbase + kb + lc];
                af[mt][1] = As[rbase + 8 * APM + kb + lc];
                af[mt][2] = As[rbase + kb + lc + 4];
                af[mt][3] = As[rbase + 8 * APM + kb + lc + 4];
            }
            #pragma unroll
            for (int nt = 0; nt < 8; nt++) {
                const int nn = warp_n * 64 + nt * 8 + lr;
                bf[nt][0] = Bs[(kb + lc) * BPN + nn];
                bf[nt][1] = Bs[(kb + lc + 4) * BPN + nn];
            }
            #pragma unroll
            for (int mt = 0; mt < 2; mt++)
                #pragma unroll
                for (int nt = 0; nt < 8; nt++)
                    mma_tf32(acc[mt][nt], af[mt], bf[nt]);
        }
        __syncthreads();
    }

    // epilogue: d0/d1 -> (row, col/col+1), d2/d3 -> (row+8, ...)
    #pragma unroll
    for (int mt = 0; mt < 2; mt++) {
        const int r = m0 + warp_m * 32 + mt * 16 + lr;
        #pragma unroll
        for (int nt = 0; nt < 8; nt++) {
            const int cc = n0 + warp_n * 64 + nt * 8 + lc * 2;
            const float b0 = bias[cc], b1 = bias[cc + 1];
            *reinterpret_cast<float2*>(C + (size_t)r * HDIM + cc) =
                make_float2(acc[mt][nt][0] + b0, acc[mt][nt][1] + b1);
            *reinterpret_cast<float2*>(C + (size_t)(r + 8) * HDIM + cc) =
                make_float2(acc[mt][nt][2] + b0, acc[mt][nt][3] + b1);
        }
    }
}

// ---------------------------------------------------------------------------
// Flash attention: 64 queries x 128 keys per iter, 256 threads, FFMA2.
// ---------------------------------------------------------------------------
static constexpr int QP = 68;
static constexpr int KP = 132;
static constexpr int VP = 68;
static constexpr int PP = 68;
static constexpr int ATTN_FLOATS = 64*QP + 64*KP + 128*VP + 128*PP + 128;
static constexpr int ATTN_SMEM = ATTN_FLOATS * 4;
static constexpr float SCALE = 0.125f;

__global__ __launch_bounds__(256)
void attn_kernel(const float* __restrict__ mask) {
    extern __shared__ float smf[];
    float* Qt = smf;
    float* Kt = Qt + 64 * QP;
    float* Vs = Kt + 64 * KP;
    float* Pt = Vs + 128 * VP;
    float* ms = Pt + 128 * PP;

    const int b = blockIdx.z, h = blockIdx.y, qt = blockIdx.x;
    const int tid = threadIdx.x;
    const int tx = tid & 15, ty = tid >> 4;
    const int i0 = ty * 4;
    const int d0 = tx * 4;
    const int j0 = tx * 8;
    const size_t qbase = (size_t)b * SD + qt * 64;

    for (int idx = tid; idx < 64 * 16; idx += 256) {
        const int q = idx >> 4, rc = (idx & 15) * 4;
        float4 v = ldf4(&g_Qlow[(qbase + q) * HDIM + h * 64 + rc]);
        Qt[(rc + 0) * QP + q] = v.x;
        Qt[(rc + 1) * QP + q] = v.y;
        Qt[(rc + 2) * QP + q] = v.z;
        Qt[(rc + 3) * QP + q] = v.w;
    }

    float m_[4], l_[4];
    ull O2[4][2];
    #pragma unroll
    for (int i = 0; i < 4; i++) {
        m_[i] = -1e30f; l_[i] = 0.f;
        O2[i][0] = 0ULL; O2[i][1] = 0ULL;
    }

    for (int kt = 0; kt < SD / 128; kt++) {
        __syncthreads();
        const size_t kb = (size_t)b * SD + kt * 128;
        for (int idx = tid; idx < 128 * 16; idx += 256) {
            const int k = idx >> 4, rc = (idx & 15) * 4;
            float4 v = ldf4(&g_Klow[(kb + k) * HDIM + h * 64 + rc]);
            Kt[(rc + 0) * KP + k] = v.x;
            Kt[(rc + 1) * KP + k] = v.y;
            Kt[(rc + 2) * KP + k] = v.z;
            Kt[(rc + 3) * KP + k] = v.w;
            *reinterpret_cast<float4*>(&Vs[k * VP + rc]) =
                ldf4(&g_V[(kb + k) * HDIM + h * 64 + rc]);
        }
        if (tid < 128) ms[tid] = mask[(size_t)b * SD + kt * 128 + tid];
        __syncthreads();

        ull s2[4][4];
        #pragma unroll
        for (int i = 0; i < 4; i++)
            #pragma unroll
            for (int jp = 0; jp < 4; jp++) s2[i][jp] = 0ULL;

        #pragma unroll 4
        for (int r = 0; r < 64; r++) {
            float4 qv = *reinterpret_cast<const float4*>(&Qt[r * QP + i0]);
            ulonglong2 ka = *reinterpret_cast<const ulonglong2*>(&Kt[r * KP + j0]);
            ulonglong2 kb2 = *reinterpret_cast<const ulonglong2*>(&Kt[r * KP + j0 + 4]);
            const ull kp[4] = {ka.x, ka.y, kb2.x, kb2.y};
            const float qs[4] = {qv.x, qv.y, qv.z, qv.w};
            #pragma unroll
            for (int i = 0; i < 4; i++) {
                ull qb = bc2(qs[i]);
                #pragma unroll
                for (int jp = 0; jp < 4; jp++) fma2(s2[i][jp], qb, kp[jp]);
            }
        }

        float s[4][8];
        #pragma unroll
        for (int i = 0; i < 4; i++)
            #pragma unroll
            for (int jp = 0; jp < 4; jp++) {
                float2 t = up2(s2[i][jp]);
                s[i][2*jp] = t.x; s[i][2*jp+1] = t.y;
            }

        float4 mr0 = *reinterpret_cast<const float4*>(&ms[j0]);
        float4 mr1 = *reinterpret_cast<const float4*>(&ms[j0 + 4]);
        const float mv[8] = {mr0.x, mr0.y, mr0.z, mr0.w, mr1.x, mr1.y, mr1.z, mr1.w};

        #pragma unroll
        for (int i = 0; i < 4; i++) {
            #pragma unroll
            for (int j = 0; j < 8; j++) s[i][j] = s[i][j] * SCALE + mv[j];
            float rm = s[i][0];
            #pragma unroll
            for (int j = 1; j < 8; j++) rm = fmaxf(rm, s[i][j]);
            #pragma unroll
            for (int w = 8; w >= 1; w >>= 1)
                rm = fmaxf(rm, __shfl_xor_sync(0xffffffffu, rm, w));
            const float mn = fmaxf(m_[i], rm);
            float rs = 0.f;
            #pragma unroll
            for (int j = 0; j < 8; j++) { s[i][j] = __expf(s[i][j] - mn); rs += s[i][j]; }
            #pragma unroll
            for (int w = 8; w >= 1; w >>= 1)
                rs += __shfl_xor_sync(0xffffffffu, rs, w);
            const float f = __expf(m_[i] - mn);
            l_[i] = l_[i] * f + rs;
            m_[i] = mn;
            ull fb = bc2(f);
            mul2(O2[i][0], fb);
            mul2(O2[i][1], fb);
        }

        #pragma unroll
        for (int jj = 0; jj < 8; jj++) {
            float4 col = make_float4(s[0][jj], s[1][jj], s[2][jj], s[3][jj]);
            *reinterpret_cast<float4*>(&Pt[(j0 + jj) * PP + i0]) = col;
        }
        __syncthreads();

        #pragma unroll 4
        for (int k = 0; k < 128; k++) {
            float4 pv = *reinterpret_cast<const float4*>(&Pt[k * PP + i0]);
            ulonglong2 vv = *reinterpret_cast<const ulonglong2*>(&Vs[k * VP + d0]);
            const float ps[4] = {pv.x, pv.y, pv.z, pv.w};
            #pragma unroll
            for (int i = 0; i < 4; i++) {
                ull pb = bc2(ps[i]);
                fma2(O2[i][0], pb, vv.x);
                fma2(O2[i][1], pb, vv.y);
            }
        }
    }

    #pragma unroll
    for (int i = 0; i < 4; i++) {
        const float inv = 1.f / l_[i];
        float2 a = up2(O2[i][0]);
        float2 c = up2(O2[i][1]);
        float4 o = make_float4(a.x * inv, a.y * inv, c.x * inv, c.y * inv);
        *reinterpret_cast<float4*>(
            &g_ctx[(qbase + i0 + i) * HDIM + h * 64 + d0]) = o;
    }
}

// ---------------------------------------------------------------------------
extern "C" void kernel_launch(void* const* d_in, const int* in_sizes, int n_in,
                              void* d_out, int out_size) {
    (void)in_sizes; (void)n_in; (void)out_size;
    const float* x    = (const float*)d_in[0];
    const float* mask = (const float*)d_in[1];
    const float* Wq   = (const float*)d_in[2];
    const float* bq   = (const float*)d_in[3];
    const float* Wk   = (const float*)d_in[4];
    const float* bk   = (const float*)d_in[5];
    const float* Wv   = (const float*)d_in[6];
    const float* bv   = (const float*)d_in[7];
    const float* Wql  = (const float*)d_in[8];
    const float* bql  = (const float*)d_in[9];
    const float* Wkl  = (const float*)d_in[10];
    const float* bkl  = (const float*)d_in[11];
    const float* Wo   = (const float*)d_in[12];
    const float* bo   = (const float*)d_in[13];
    float* out = (float*)d_out;

    float *pWqEff, *pWkEff, *pbqEff, *pbkEff, *pQ, *pK, *pV, *pCtx;
    cudaGetSymbolAddress((void**)&pWqEff, g_WqEff);
    cudaGetSymbolAddress((void**)&pWkEff, g_WkEff);
    cudaGetSymbolAddress((void**)&pbqEff, g_bqEff);
    cudaGetSymbolAddress((void**)&pbkEff, g_bkEff);
    cudaGetSymbolAddress((void**)&pQ,    g_Qlow);
    cudaGetSymbolAddress((void**)&pK,    g_Klow);
    cudaGetSymbolAddress((void**)&pV,    g_V);
    cudaGetSymbolAddress((void**)&pCtx,  g_ctx);

    cudaFuncSetAttribute(attn_kernel,
                         cudaFuncAttributeMaxDynamicSharedMemorySize, ATTN_SMEM);

    weff_kernel<<<dim3(HDIM / 4, NHD), 256>>>(Wq, Wql, bq, bql, pWqEff, pbqEff);
    weff_kernel<<<dim3(HDIM / 4, NHD), 256>>>(Wk, Wkl, bk, bkl, pWkEff, pbkEff);

    const dim3 gg(HDIM / 128, MD / 128);
    mma_gemm_bias<<<gg, 256>>>(x, pWqEff, pbqEff, pQ);
    mma_gemm_bias<<<gg, 256>>>(x, pWkEff, pbkEff, pK);
    mma_gemm_bias<<<gg, 256>>>(x, Wv, bv, pV);

    attn_kernel<<<dim3(SD / 64, NHD, BD), 256, ATTN_SMEM>>>(mask);

    mma_gemm_bias<<<gg, 256>>>(pCtx, Wo, bo, out);
}

// round 11
// speedup vs baseline: 4.5353x; 2.3319x over previous
#include <cuda_runtime.h>
#include <math.h>
#include <stdint.h>

#define BD 2
#define SD 2048
#define HDIM 1024
#define NHD 16
#define HDD 64
#define RD 64
#define MD (BD*SD)   /* 4096 */

typedef unsigned long long ull;

static __device__ __forceinline__ float4 ldf4(const float* p) {
    return *reinterpret_cast<const float4*>(p);
}
static __device__ __forceinline__ uint32_t cvt_tf32(float v) {
    uint32_t r; asm("cvt.rna.tf32.f32 %0, %1;" : "=r"(r) : "f"(v)); return r;
}
// m16n8k8 tf32 mma (sm_80+ PTX, valid on compute_103)
static __device__ __forceinline__ void mma_tf32(float* d, const uint32_t* a,
                                                const uint32_t* b) {
    asm volatile(
        "mma.sync.aligned.m16n8k8.row.col.f32.tf32.tf32.f32 "
        "{%0,%1,%2,%3}, {%4,%5,%6,%7}, {%8,%9}, {%0,%1,%2,%3};"
        : "+f"(d[0]), "+f"(d[1]), "+f"(d[2]), "+f"(d[3])
        : "r"(a[0]), "r"(a[1]), "r"(a[2]), "r"(a[3]), "r"(b[0]), "r"(b[1]));
}

// ---------------- scratch (device globals; no allocation allowed) ----------
__device__ float g_WqEff[HDIM*HDIM];
__device__ float g_WkEff[HDIM*HDIM];
__device__ float g_bqEff[HDIM];
__device__ float g_bkEff[HDIM];
__device__ float g_Qlow[(size_t)MD*HDIM];
__device__ float g_Klow[(size_t)MD*HDIM];
__device__ float g_V   [(size_t)MD*HDIM];
__device__ float g_ctx [(size_t)MD*HDIM];

// ---------------------------------------------------------------------------
// Effective low-rank weights
// ---------------------------------------------------------------------------
__global__ void weff_kernel(const float* __restrict__ W,
                            const float* __restrict__ Wl,
                            const float* __restrict__ b,
                            const float* __restrict__ bl,
                            float* __restrict__ Weff,
                            float* __restrict__ beff) {
    __shared__ float Wls[HDD*RD];
    const int h  = blockIdx.y;
    const int r  = threadIdx.x & 63;
    const int kr = threadIdx.x >> 6;
    for (int i = threadIdx.x; i < HDD*RD; i += 256) Wls[i] = Wl[i];
    __syncthreads();
    const int k = blockIdx.x * 4 + kr;
    const float* wrow = W + (size_t)k*HDIM + h*HDD;
    float acc = 0.f;
    #pragma unroll
    for (int d = 0; d < HDD; d++) acc += wrow[d] * Wls[d*RD + r];
    Weff[(size_t)k*HDIM + h*RD + r] = acc;
    if (blockIdx.x == 0 && kr == 0) {
        float bacc = bl[r];
        #pragma unroll
        for (int d = 0; d < HDD; d++) bacc += b[h*HDD + d] * Wls[d*RD + r];
        beff[h*RD + r] = bacc;
    }
}

// ---------------------------------------------------------------------------
// mma.sync tf32 GEMM: C[4096,1024] = A @ W + bias.  (unchanged from R10)
// ---------------------------------------------------------------------------
static constexpr int APM = 36;
static constexpr int BPN = 132;

__global__ __launch_bounds__(256, 2)
void mma_gemm_bias(const float* __restrict__ A, const float* __restrict__ W,
                   const float* __restrict__ bias, float* __restrict__ C) {
    __shared__ uint32_t As[128 * APM];
    __shared__ uint32_t Bs[32 * BPN];

    const int tid = threadIdx.x;
    const int wid = tid >> 5, lane = tid & 31;
    const int lr = lane >> 2, lc = lane & 3;
    const int warp_m = wid & 3, warp_n = wid >> 2;
    const int m0 = blockIdx.y * 128, n0 = blockIdx.x * 128;

    float acc[2][8][4];
    #pragma unroll
    for (int mt = 0; mt < 2; mt++)
        #pragma unroll
        for (int nt = 0; nt < 8; nt++)
            #pragma unroll
            for (int e = 0; e < 4; e++) acc[mt][nt][e] = 0.f;

    for (int k0 = 0; k0 < HDIM; k0 += 32) {
        #pragma unroll
        for (int it = 0; it < 4; it++) {
            const int idx = it * 256 + tid;
            const int m = idx >> 3, k4 = idx & 7;
            float4 v = ldf4(A + (size_t)(m0 + m) * HDIM + k0 + k4 * 4);
            uint4 t = make_uint4(cvt_tf32(v.x), cvt_tf32(v.y),
                                 cvt_tf32(v.z), cvt_tf32(v.w));
            *reinterpret_cast<uint4*>(&As[m * APM + k4 * 4]) = t;
        }
        #pragma unroll
        for (int it = 0; it < 4; it++) {
            const int idx = it * 256 + tid;
            const int kr = idx >> 5, n4 = idx & 31;
            float4 v = ldf4(W + (size_t)(k0 + kr) * HDIM + n0 + n4 * 4);
            uint4 t = make_uint4(cvt_tf32(v.x), cvt_tf32(v.y),
                                 cvt_tf32(v.z), cvt_tf32(v.w));
            *reinterpret_cast<uint4*>(&Bs[kr * BPN + n4 * 4]) = t;
        }
        __syncthreads();

        #pragma unroll
        for (int ks = 0; ks < 4; ks++) {
            const int kb = ks * 8;
            uint32_t af[2][4], bf[8][2];
            #pragma unroll
            for (int mt = 0; mt < 2; mt++) {
                const int rbase = (warp_m * 32 + mt * 16 + lr) * APM;
                af[mt][0] = As[rbase + kb + lc];
                af[mt][1] = As[rbase + 8 * APM + kb + lc];
                af[mt][2] = As[rbase + kb + lc + 4];
                af[mt][3] = As[rbase + 8 * APM + kb + lc + 4];
            }
            #pragma unroll
            for (int nt = 0; nt < 8; nt++) {
                const int nn = warp_n * 64 + nt * 8 + lr;
                bf[nt][0] = Bs[(kb + lc) * BPN + nn];
                bf[nt][1] = Bs[(kb + lc + 4) * BPN + nn];
            }
            #pragma unroll
            for (int mt = 0; mt < 2; mt++)
                #pragma unroll
                for (int nt = 0; nt < 8; nt++)
                    mma_tf32(acc[mt][nt], af[mt], bf[nt]);
        }
        __syncthreads();
    }

    #pragma unroll
    for (int mt = 0; mt < 2; mt++) {
        const int r = m0 + warp_m * 32 + mt * 16 + lr;
        #pragma unroll
        for (int nt = 0; nt < 8; nt++) {
            const int cc = n0 + warp_n * 64 + nt * 8 + lc * 2;
            const float b0 = bias[cc], b1 = bias[cc + 1];
            *reinterpret_cast<float2*>(C + (size_t)r * HDIM + cc) =
                make_float2(acc[mt][nt][0] + b0, acc[mt][nt][1] + b1);
            *reinterpret_cast<float2*>(C + (size_t)(r + 8) * HDIM + cc) =
                make_float2(acc[mt][nt][2] + b0, acc[mt][nt][3] + b1);
        }
    }
}

// ---------------------------------------------------------------------------
// Tensor-core flash attention.
// CTA: 128 queries, 8 warps (warp w -> rows w*16..w*16+15). 32 iters of 64 keys.
// All smem tiles pitch 68 -> conflict-free mma fragment loads.
//   Qs[q][r], Ks[key][r] (natural = col-major B for QK), Vs[key][d],
//   Ps[q][key] (A operand of PV).
// ---------------------------------------------------------------------------
static constexpr int QP2 = 68, KP2 = 68, VP2 = 68, PP2 = 68;
static constexpr int ATTN_WORDS = 128*QP2 + 64*KP2 + 64*VP2 + 128*PP2 + 64;
static constexpr int ATTN_SMEM  = ATTN_WORDS * 4;   /* 104,960 B */
static constexpr float SCALE = 0.125f;              /* 1/sqrt(64) */

__global__ __launch_bounds__(256)
void attn_mma_kernel(const float* __restrict__ mask) {
    extern __shared__ uint32_t sm2[];
    uint32_t* Qs = sm2;
    uint32_t* Ks = Qs + 128 * QP2;
    uint32_t* Vs = Ks + 64 * KP2;
    uint32_t* Ps = Vs + 64 * VP2;
    float*    ms = reinterpret_cast<float*>(Ps + 128 * PP2);

    const int b = blockIdx.z, h = blockIdx.y, qt = blockIdx.x;
    const int tid = threadIdx.x;
    const int wid = tid >> 5, lane = tid & 31;
    const int lr = lane >> 2, lc = lane & 3;
    const int row0 = wid * 16 + lr;
    const size_t qbase = (size_t)b * SD + qt * 128;

    // stage Q once (tf32)
    for (int idx = tid; idx < 128 * 16; idx += 256) {
        const int q = idx >> 4, rc = (idx & 15) * 4;
        float4 v = ldf4(&g_Qlow[(qbase + q) * HDIM + h * 64 + rc]);
        uint4 t = make_uint4(cvt_tf32(v.x), cvt_tf32(v.y),
                             cvt_tf32(v.z), cvt_tf32(v.w));
        *reinterpret_cast<uint4*>(&Qs[q * QP2 + rc]) = t;
    }

    float Ofr[8][4];
    #pragma unroll
    for (int nt = 0; nt < 8; nt++)
        #pragma unroll
        for (int e = 0; e < 4; e++) Ofr[nt][e] = 0.f;
    float m_[2] = {-1e30f, -1e30f}, l_[2] = {0.f, 0.f};

    for (int kt = 0; kt < SD / 64; kt++) {
        __syncthreads();                       // prev iter done with Ks/Vs/Ps
        const size_t kb0 = (size_t)b * SD + kt * 64;
        #pragma unroll
        for (int it = 0; it < 4; it++) {
            const int idx = it * 256 + tid;
            const int k = idx >> 4, rc = (idx & 15) * 4;
            float4 v = ldf4(&g_Klow[(kb0 + k) * HDIM + h * 64 + rc]);
            *reinterpret_cast<uint4*>(&Ks[k * KP2 + rc]) =
                make_uint4(cvt_tf32(v.x), cvt_tf32(v.y), cvt_tf32(v.z), cvt_tf32(v.w));
            float4 w = ldf4(&g_V[(kb0 + k) * HDIM + h * 64 + rc]);
            *reinterpret_cast<uint4*>(&Vs[k * VP2 + rc]) =
                make_uint4(cvt_tf32(w.x), cvt_tf32(w.y), cvt_tf32(w.z), cvt_tf32(w.w));
        }
        if (tid < 64) ms[tid] = mask[(size_t)b * SD + kt * 64 + tid];
        __syncthreads();

        // ---- S = Q . K^T -------------------------------------------------
        float sfr[8][4];
        #pragma unroll
        for (int nt = 0; nt < 8; nt++)
            #pragma unroll
            for (int e = 0; e < 4; e++) sfr[nt][e] = 0.f;

        #pragma unroll
        for (int ks = 0; ks < 8; ks++) {
            const int kb = ks * 8;
            uint32_t af[4];
            const uint32_t* qr = &Qs[row0 * QP2 + kb + lc];
            af[0] = qr[0]; af[1] = qr[8 * QP2]; af[2] = qr[4]; af[3] = qr[8 * QP2 + 4];
            #pragma unroll
            for (int nt = 0; nt < 8; nt++) {
                uint32_t bf[2];
                const uint32_t* kr2 = &Ks[(nt * 8 + lr) * KP2 + kb + lc];
                bf[0] = kr2[0]; bf[1] = kr2[4];
                mma_tf32(sfr[nt], af, bf);
            }
        }

        // ---- online softmax on fragments ---------------------------------
        float mv[8][2];
        #pragma unroll
        for (int nt = 0; nt < 8; nt++) {
            float2 mm = *reinterpret_cast<const float2*>(&ms[nt * 8 + 2 * lc]);
            mv[nt][0] = mm.x; mv[nt][1] = mm.y;
        }

        #pragma unroll
        for (int rr = 0; rr < 2; rr++) {
            float rm = -1e30f;
            #pragma unroll
            for (int nt = 0; nt < 8; nt++)
                #pragma unroll
                for (int e = 0; e < 2; e++) {
                    float v = sfr[nt][rr * 2 + e] * SCALE + mv[nt][e];
                    sfr[nt][rr * 2 + e] = v;
                    rm = fmaxf(rm, v);
                }
            rm = fmaxf(rm, __shfl_xor_sync(0xffffffffu, rm, 1));
            rm = fmaxf(rm, __shfl_xor_sync(0xffffffffu, rm, 2));
            const float mn = fmaxf(m_[rr], rm);
            float rs = 0.f;
            #pragma unroll
            for (int nt = 0; nt < 8; nt++)
                #pragma unroll
                for (int e = 0; e < 2; e++) {
                    float p = __expf(sfr[nt][rr * 2 + e] - mn);
                    sfr[nt][rr * 2 + e] = p;
                    rs += p;
                }
            rs += __shfl_xor_sync(0xffffffffu, rs, 1);
            rs += __shfl_xor_sync(0xffffffffu, rs, 2);
            const float f = __expf(m_[rr] - mn);
            l_[rr] = l_[rr] * f + rs;
            m_[rr] = mn;
            #pragma unroll
            for (int nt = 0; nt < 8; nt++) {
                Ofr[nt][rr * 2 + 0] *= f;
                Ofr[nt][rr * 2 + 1] *= f;
            }
        }

        // ---- P -> smem (tf32) --------------------------------------------
        #pragma unroll
        for (int nt = 0; nt < 8; nt++) {
            uint2 p0 = make_uint2(cvt_tf32(sfr[nt][0]), cvt_tf32(sfr[nt][1]));
            *reinterpret_cast<uint2*>(&Ps[row0 * PP2 + nt * 8 + 2 * lc]) = p0;
            uint2 p1 = make_uint2(cvt_tf32(sfr[nt][2]), cvt_tf32(sfr[nt][3]));
            *reinterpret_cast<uint2*>(&Ps[(row0 + 8) * PP2 + nt * 8 + 2 * lc]) = p1;
        }
        __syncthreads();

        // ---- O += P . V ---------------------------------------------------
        #pragma unroll
        for (int ks = 0; ks < 8; ks++) {
            const int kb = ks * 8;
            uint32_t af[4];
            const uint32_t* pr = &Ps[row0 * PP2 + kb + lc];
            af[0] = pr[0]; af[1] = pr[8 * PP2]; af[2] = pr[4]; af[3] = pr[8 * PP2 + 4];
            #pragma unroll
            for (int nt = 0; nt < 8; nt++) {
                uint32_t bf[2];
                const uint32_t* vr = &Vs[(kb + lc) * VP2 + nt * 8 + lr];
                bf[0] = vr[0]; bf[1] = vr[4 * VP2];
                mma_tf32(Ofr[nt], af, bf);
            }
        }
    }

    const float inv0 = 1.f / l_[0], inv1 = 1.f / l_[1];
    const size_t rg = (qbase + row0) * HDIM + h * 64;
    #pragma unroll
    for (int nt = 0; nt < 8; nt++) {
        *reinterpret_cast<float2*>(&g_ctx[rg + nt * 8 + 2 * lc]) =
            make_float2(Ofr[nt][0] * inv0, Ofr[nt][1] * inv0);
        *reinterpret_cast<float2*>(&g_ctx[rg + 8 * HDIM + nt * 8 + 2 * lc]) =
            make_float2(Ofr[nt][2] * inv1, Ofr[nt][3] * inv1);
    }
}

// ---------------------------------------------------------------------------
extern "C" void kernel_launch(void* const* d_in, const int* in_sizes, int n_in,
                              void* d_out, int out_size) {
    (void)in_sizes; (void)n_in; (void)out_size;
    const float* x    = (const float*)d_in[0];
    const float* mask = (const float*)d_in[1];
    const float* Wq   = (const float*)d_in[2];
    const float* bq   = (const float*)d_in[3];
    const float* Wk   = (const float*)d_in[4];
    const float* bk   = (const float*)d_in[5];
    const float* Wv   = (const float*)d_in[6];
    const float* bv   = (const float*)d_in[7];
    const float* Wql  = (const float*)d_in[8];
    const float* bql  = (const float*)d_in[9];
    const float* Wkl  = (const float*)d_in[10];
    const float* bkl  = (const float*)d_in[11];
    const float* Wo   = (const float*)d_in[12];
    const float* bo   = (const float*)d_in[13];
    float* out = (float*)d_out;

    float *pWqEff, *pWkEff, *pbqEff, *pbkEff, *pQ, *pK, *pV, *pCtx;
    cudaGetSymbolAddress((void**)&pWqEff, g_WqEff);
    cudaGetSymbolAddress((void**)&pWkEff, g_WkEff);
    cudaGetSymbolAddress((void**)&pbqEff, g_bqEff);
    cudaGetSymbolAddress((void**)&pbkEff, g_bkEff);
    cudaGetSymbolAddress((void**)&pQ,    g_Qlow);
    cudaGetSymbolAddress((void**)&pK,    g_Klow);
    cudaGetSymbolAddress((void**)&pV,    g_V);
    cudaGetSymbolAddress((void**)&pCtx,  g_ctx);

    cudaFuncSetAttribute(attn_mma_kernel,
                         cudaFuncAttributeMaxDynamicSharedMemorySize, ATTN_SMEM);

    weff_kernel<<<dim3(HDIM / 4, NHD), 256>>>(Wq, Wql, bq, bql, pWqEff, pbqEff);
    weff_kernel<<<dim3(HDIM / 4, NHD), 256>>>(Wk, Wkl, bk, bkl, pWkEff, pbkEff);

    const dim3 gg(HDIM / 128, MD / 128);
    mma_gemm_bias<<<gg, 256>>>(x, pWqEff, pbqEff, pQ);
    mma_gemm_bias<<<gg, 256>>>(x, pWkEff, pbkEff, pK);
    mma_gemm_bias<<<gg, 256>>>(x, Wv, bv, pV);

    attn_mma_kernel<<<dim3(SD / 128, NHD, BD), 256, ATTN_SMEM>>>(mask);

    mma_gemm_bias<<<gg, 256>>>(pCtx, Wo, bo, out);
}

// round 13
// speedup vs baseline: 4.5477x; 1.0027x over previous
#include <cuda_runtime.h>
#include <math.h>
#include <stdint.h>

#define BD 2
#define SD 2048
#define HDIM 1024
#define NHD 16
#define HDD 64
#define RD 64
#define MD (BD*SD)   /* 4096 */

typedef unsigned long long ull;

static __device__ __forceinline__ float4 ldf4(const float* p) {
    return *reinterpret_cast<const float4*>(p);
}
static __device__ __forceinline__ uint32_t cvt_tf32(float v) {
    uint32_t r; asm("cvt.rna.tf32.f32 %0, %1;" : "=r"(r) : "f"(v)); return r;
}
static __device__ __forceinline__ float rnd_tf32(float v) {
    return __uint_as_float(cvt_tf32(v));
}
// m16n8k8 tf32 mma (sm_80+ PTX, valid on compute_103)
static __device__ __forceinline__ void mma_tf32(float* d, const uint32_t* a,
                                                const uint32_t* b) {
    asm volatile(
        "mma.sync.aligned.m16n8k8.row.col.f32.tf32.tf32.f32 "
        "{%0,%1,%2,%3}, {%4,%5,%6,%7}, {%8,%9}, {%0,%1,%2,%3};"
        : "+f"(d[0]), "+f"(d[1]), "+f"(d[2]), "+f"(d[3])
        : "r"(a[0]), "r"(a[1]), "r"(a[2]), "r"(a[3]), "r"(b[0]), "r"(b[1]));
}
static __device__ __forceinline__ uint32_t smem_u32(const void* p) {
    uint32_t a;
    asm("{ .reg .u64 t; cvta.to.shared.u64 t, %1; cvt.u32.u64 %0, t; }"
        : "=r"(a) : "l"(p));
    return a;
}
static __device__ __forceinline__ void cp16(uint32_t dst, const void* src) {
    asm volatile("cp.async.cg.shared.global [%0], [%1], 16;"
                 :: "r"(dst), "l"(src) : "memory");
}
#define CP_COMMIT() asm volatile("cp.async.commit_group;" ::: "memory")
#define CP_WAIT1()  asm volatile("cp.async.wait_group 1;" ::: "memory")
#define CP_WAIT0()  asm volatile("cp.async.wait_group 0;" ::: "memory")

// ---------------- scratch (device globals; no allocation allowed) ----------
__device__ float g_WqEff[HDIM*HDIM];
__device__ float g_WkEff[HDIM*HDIM];
__device__ float g_bqEff[HDIM];
__device__ float g_bkEff[HDIM];
__device__ float g_Qlow[(size_t)MD*HDIM];
__device__ float g_Klow[(size_t)MD*HDIM];
__device__ float g_V   [(size_t)MD*HDIM];
__device__ float g_ctx [(size_t)MD*HDIM];
__device__ float g_xr  [(size_t)MD*HDIM];   // tf32-rounded x
__device__ float g_Wvr [HDIM*HDIM];         // tf32-rounded Wv
__device__ float g_Wor [HDIM*HDIM];         // tf32-rounded Wo

// ---------------------------------------------------------------------------
// Elementwise tf32 (RNA) rounding: out[i] = tf32(in[i])
// ---------------------------------------------------------------------------
__global__ void round_tf32_kernel(const float* __restrict__ in,
                                  float* __restrict__ out, int n4) {
    int i = blockIdx.x * 256 + threadIdx.x;
    if (i < n4) {
        float4 v = ldf4(in + (size_t)i * 4);
        float4 o = make_float4(rnd_tf32(v.x), rnd_tf32(v.y),
                               rnd_tf32(v.z), rnd_tf32(v.w));
        *reinterpret_cast<float4*>(out + (size_t)i * 4) = o;
    }
}

// ---------------------------------------------------------------------------
// Effective low-rank weights (output rounded to tf32)
// ---------------------------------------------------------------------------
__global__ void weff_kernel(const float* __restrict__ W,
                            const float* __restrict__ Wl,
                            const float* __restrict__ b,
                            const float* __restrict__ bl,
                            float* __restrict__ Weff,
                            float* __restrict__ beff) {
    __shared__ float Wls[HDD*RD];
    const int h  = blockIdx.y;
    const int r  = threadIdx.x & 63;
    const int kr = threadIdx.x >> 6;
    for (int i = threadIdx.x; i < HDD*RD; i += 256) Wls[i] = Wl[i];
    __syncthreads();
    const int k = blockIdx.x * 4 + kr;
    const float* wrow = W + (size_t)k*HDIM + h*HDD;
    float acc = 0.f;
    #pragma unroll
    for (int d = 0; d < HDD; d++) acc += wrow[d] * Wls[d*RD + r];
    Weff[(size_t)k*HDIM + h*RD + r] = rnd_tf32(acc);
    if (blockIdx.x == 0 && kr == 0) {
        float bacc = bl[r];
        #pragma unroll
        for (int d = 0; d < HDD; d++) bacc += b[h*HDD + d] * Wls[d*RD + r];
        beff[h*RD + r] = bacc;
    }
}

// ---------------------------------------------------------------------------
// cp.async double-buffered tf32 GEMM: C = A @ W + bias, A/W pre-rounded tf32.
// CTA 128x128, BK=32, 8 warps 4(m)x2(n), warp tile 32x64.
// grid.z selects (W, bias, C) -> fuses the 3 projection GEMMs in one launch.
// ---------------------------------------------------------------------------
static constexpr int APM = 36;    // A smem pitch
static constexpr int BPN = 132;   // B smem pitch

template<bool ROUND>
__global__ __launch_bounds__(256, 2)
void gemm_pipe(const float* __restrict__ A,
               const float* __restrict__ W0, const float* __restrict__ W1,
               const float* __restrict__ W2,
               const float* __restrict__ B0, const float* __restrict__ B1,
               const float* __restrict__ B2,
               float* __restrict__ C0, float* __restrict__ C1,
               float* __restrict__ C2) {
    __shared__ uint32_t As[2][128 * APM];
    __shared__ uint32_t Bs[2][32 * BPN];

    const float* W = (blockIdx.z == 0) ? W0 : (blockIdx.z == 1) ? W1 : W2;
    const float* bias = (blockIdx.z == 0) ? B0 : (blockIdx.z == 1) ? B1 : B2;
    float* C = (blockIdx.z == 0) ? C0 : (blockIdx.z == 1) ? C1 : C2;

    const int tid = threadIdx.x;
    const int wid = tid >> 5, lane = tid & 31;
    const int lr = lane >> 2, lc = lane & 3;
    const int warp_m = wid & 3, warp_n = wid >> 2;
    const int m0 = blockIdx.y * 128, n0 = blockIdx.x * 128;

    const uint32_t aS[2] = {smem_u32(As[0]), smem_u32(As[1])};
    const uint32_t bS[2] = {smem_u32(Bs[0]), smem_u32(Bs[1])};

    const int am = tid >> 3, ak4 = tid & 7;       // A: 4 chunks of 32 rows
    const int bk = tid >> 5, bn4 = tid & 31;      // B: 4 chunks of 8 k-rows

    auto issue = [&](int c) {
        const int k0 = c * 32, buf = c & 1;
        #pragma unroll
        for (int it = 0; it < 4; it++) {
            const int m = it * 32 + am;
            cp16(aS[buf] + (uint32_t)(m * APM + ak4 * 4) * 4,
                 A + (size_t)(m0 + m) * HDIM + k0 + ak4 * 4);
        }
        #pragma unroll
        for (int it = 0; it < 4; it++) {
            const int kr = it * 8 + bk;
            cp16(bS[buf] + (uint32_t)(kr * BPN + bn4 * 4) * 4,
                 W + (size_t)(k0 + kr) * HDIM + n0 + bn4 * 4);
        }
        CP_COMMIT();
    };

    float acc[2][8][4];
    #pragma unroll
    for (int mt = 0; mt < 2; mt++)
        #pragma unroll
        for (int nt = 0; nt < 8; nt++)
            #pragma unroll
            for (int e = 0; e < 4; e++) acc[mt][nt][e] = 0.f;

    issue(0);
    for (int c = 0; c < 32; c++) {
        if (c < 31) { issue(c + 1); CP_WAIT1(); } else { CP_WAIT0(); }
        __syncthreads();

        const uint32_t* Ab = As[c & 1];
        const uint32_t* Bb = Bs[c & 1];
        #pragma unroll
        for (int ks = 0; ks < 4; ks++) {
            const int kb = ks * 8;
            uint32_t af[2][4], bf[8][2];
            #pragma unroll
            for (int mt = 0; mt < 2; mt++) {
                const int rbase = (warp_m * 32 + mt * 16 + lr) * APM;
                af[mt][0] = Ab[rbase + kb + lc];
                af[mt][1] = Ab[rbase + 8 * APM + kb + lc];
                af[mt][2] = Ab[rbase + kb + lc + 4];
                af[mt][3] = Ab[rbase + 8 * APM + kb + lc + 4];
            }
            #pragma unroll
            for (int nt = 0; nt < 8; nt++) {
                const int nn = warp_n * 64 + nt * 8 + lr;
                bf[nt][0] = Bb[(kb + lc) * BPN + nn];
                bf[nt][1] = Bb[(kb + lc + 4) * BPN + nn];
            }
            #pragma unroll
            for (int mt = 0; mt < 2; mt++)
                #pragma unroll
                for (int nt = 0; nt < 8; nt++)
                    mma_tf32(acc[mt][nt], af[mt], bf[nt]);
        }
        __syncthreads();
    }

    #pragma unroll
    for (int mt = 0; mt < 2; mt++) {
        const int r = m0 + warp_m * 32 + mt * 16 + lr;
        #pragma unroll
        for (int nt = 0; nt < 8; nt++) {
            const int cc = n0 + warp_n * 64 + nt * 8 + lc * 2;
            const float b0 = bias[cc], b1 = bias[cc + 1];
            float2 v0, v1;
            if (ROUND) {
                v0 = make_float2(rnd_tf32(acc[mt][nt][0] + b0),
                                 rnd_tf32(acc[mt][nt][1] + b1));
                v1 = make_float2(rnd_tf32(acc[mt][nt][2] + b0),
                                 rnd_tf32(acc[mt][nt][3] + b1));
            } else {
                v0 = make_float2(acc[mt][nt][0] + b0, acc[mt][nt][1] + b1);
                v1 = make_float2(acc[mt][nt][2] + b0, acc[mt][nt][3] + b1);
            }
            *reinterpret_cast<float2*>(C + (size_t)r * HDIM + cc) = v0;
            *reinterpret_cast<float2*>(C + (size_t)(r + 8) * HDIM + cc) = v1;
        }
    }
}

// ---------------------------------------------------------------------------
// Tensor-core flash attention (inputs pre-rounded tf32 -> raw staging).
// CTA: 128 queries, 8 warps (16 rows each), 32 iters of 64 keys.
// ---------------------------------------------------------------------------
static constexpr int QP2 = 68, KP2 = 68, VP2 = 68, PP2 = 68;
static constexpr int ATTN_WORDS = 128*QP2 + 64*KP2 + 64*VP2 + 128*PP2 + 64;
static constexpr int ATTN_SMEM  = ATTN_WORDS * 4;
static constexpr float SCALE = 0.125f;

__global__ __launch_bounds__(256, 2)
void attn_mma_kernel(const float* __restrict__ mask) {
    extern __shared__ uint32_t sm2[];
    uint32_t* Qs = sm2;
    uint32_t* Ks = Qs + 128 * QP2;
    uint32_t* Vs = Ks + 64 * KP2;
    uint32_t* Ps = Vs + 64 * VP2;
    float*    ms = reinterpret_cast<float*>(Ps + 128 * PP2);

    const int b = blockIdx.z, h = blockIdx.y, qt = blockIdx.x;
    const int tid = threadIdx.x;
    const int wid = tid >> 5, lane = tid & 31;
    const int lr = lane >> 2, lc = lane & 3;
    const int row0 = wid * 16 + lr;
    const size_t qbase = (size_t)b * SD + qt * 128;

    // stage Q once (raw: already tf32 bits)
    for (int idx = tid; idx < 128 * 16; idx += 256) {
        const int q = idx >> 4, rc = (idx & 15) * 4;
        *reinterpret_cast<float4*>(&Qs[q * QP2 + rc]) =
            ldf4(&g_Qlow[(qbase + q) * HDIM + h * 64 + rc]);
    }

    float Ofr[8][4];
    #pragma unroll
    for (int nt = 0; nt < 8; nt++)
        #pragma unroll
        for (int e = 0; e < 4; e++) Ofr[nt][e] = 0.f;
    float m_[2] = {-1e30f, -1e30f}, l_[2] = {0.f, 0.f};

    for (int kt = 0; kt < SD / 64; kt++) {
        __syncthreads();
        const size_t kb0 = (size_t)b * SD + kt * 64;
        #pragma unroll
        for (int it = 0; it < 4; it++) {
            const int idx = it * 256 + tid;
            const int k = idx >> 4, rc = (idx & 15) * 4;
            *reinterpret_cast<float4*>(&Ks[k * KP2 + rc]) =
                ldf4(&g_Klow[(kb0 + k) * HDIM + h * 64 + rc]);
            *reinterpret_cast<float4*>(&Vs[k * VP2 + rc]) =
                ldf4(&g_V[(kb0 + k) * HDIM + h * 64 + rc]);
        }
        if (tid < 64) ms[tid] = mask[(size_t)b * SD + kt * 64 + tid];
        __syncthreads();

        // ---- S = Q . K^T -------------------------------------------------
        float sfr[8][4];
        #pragma unroll
        for (int nt = 0; nt < 8; nt++)
            #pragma unroll
            for (int e = 0; e < 4; e++) sfr[nt][e] = 0.f;

        #pragma unroll
        for (int ks = 0; ks < 8; ks++) {
            const int kb = ks * 8;
            uint32_t af[4];
            const uint32_t* qr = &Qs[row0 * QP2 + kb + lc];
            af[0] = qr[0]; af[1] = qr[8 * QP2]; af[2] = qr[4]; af[3] = qr[8 * QP2 + 4];
            #pragma unroll
            for (int nt = 0; nt < 8; nt++) {
                uint32_t bf[2];
                const uint32_t* kr2 = &Ks[(nt * 8 + lr) * KP2 + kb + lc];
                bf[0] = kr2[0]; bf[1] = kr2[4];
                mma_tf32(sfr[nt], af, bf);
            }
        }

        // ---- online softmax ----------------------------------------------
        float mv[8][2];
        #pragma unroll
        for (int nt = 0; nt < 8; nt++) {
            float2 mm = *reinterpret_cast<const float2*>(&ms[nt * 8 + 2 * lc]);
            mv[nt][0] = mm.x; mv[nt][1] = mm.y;
        }

        #pragma unroll
        for (int rr = 0; rr < 2; rr++) {
            float rm = -1e30f;
            #pragma unroll
            for (int nt = 0; nt < 8; nt++)
                #pragma unroll
                for (int e = 0; e < 2; e++) {
                    float v = sfr[nt][rr * 2 + e] * SCALE + mv[nt][e];
                    sfr[nt][rr * 2 + e] = v;
                    rm = fmaxf(rm, v);
                }
            rm = fmaxf(rm, __shfl_xor_sync(0xffffffffu, rm, 1));
            rm = fmaxf(rm, __shfl_xor_sync(0xffffffffu, rm, 2));
            const float mn = fmaxf(m_[rr], rm);
            float rs = 0.f;
            #pragma unroll
            for (int nt = 0; nt < 8; nt++)
                #pragma unroll
                for (int e = 0; e < 2; e++) {
                    float p = __expf(sfr[nt][rr * 2 + e] - mn);
                    sfr[nt][rr * 2 + e] = p;
                    rs += p;
                }
            rs += __shfl_xor_sync(0xffffffffu, rs, 1);
            rs += __shfl_xor_sync(0xffffffffu, rs, 2);
            const float f = __expf(m_[rr] - mn);
            l_[rr] = l_[rr] * f + rs;
            m_[rr] = mn;
            #pragma unroll
            for (int nt = 0; nt < 8; nt++) {
                Ofr[nt][rr * 2 + 0] *= f;
                Ofr[nt][rr * 2 + 1] *= f;
            }
        }

        // ---- P -> smem (tf32 RNA) ----------------------------------------
        #pragma unroll
        for (int nt = 0; nt < 8; nt++) {
            uint2 p0 = make_uint2(cvt_tf32(sfr[nt][0]), cvt_tf32(sfr[nt][1]));
            *reinterpret_cast<uint2*>(&Ps[row0 * PP2 + nt * 8 + 2 * lc]) = p0;
            uint2 p1 = make_uint2(cvt_tf32(sfr[nt][2]), cvt_tf32(sfr[nt][3]));
            *reinterpret_cast<uint2*>(&Ps[(row0 + 8) * PP2 + nt * 8 + 2 * lc]) = p1;
        }
        __syncthreads();

        // ---- O += P . V ---------------------------------------------------
        #pragma unroll
        for (int ks = 0; ks < 8; ks++) {
            const int kb = ks * 8;
            uint32_t af[4];
            const uint32_t* pr = &Ps[row0 * PP2 + kb + lc];
            af[0] = pr[0]; af[1] = pr[8 * PP2]; af[2] = pr[4]; af[3] = pr[8 * PP2 + 4];
            #pragma unroll
            for (int nt = 0; nt < 8; nt++) {
                uint32_t bf[2];
                const uint32_t* vr = &Vs[(kb + lc) * VP2 + nt * 8 + lr];
                bf[0] = vr[0]; bf[1] = vr[4 * VP2];
                mma_tf32(Ofr[nt], af, bf);
            }
        }
    }

    // epilogue: normalize + round to tf32 (ctx feeds the Wo GEMM)
    const float inv0 = 1.f / l_[0], inv1 = 1.f / l_[1];
    const size_t rg = (qbase + row0) * HDIM + h * 64;
    #pragma unroll
    for (int nt = 0; nt < 8; nt++) {
        *reinterpret_cast<float2*>(&g_ctx[rg + nt * 8 + 2 * lc]) =
            make_float2(rnd_tf32(Ofr[nt][0] * inv0), rnd_tf32(Ofr[nt][1] * inv0));
        *reinterpret_cast<float2*>(&g_ctx[rg + 8 * HDIM + nt * 8 + 2 * lc]) =
            make_float2(rnd_tf32(Ofr[nt][2] * inv1), rnd_tf32(Ofr[nt][3] * inv1));
    }
}

// ---------------------------------------------------------------------------
extern "C" void kernel_launch(void* const* d_in, const int* in_sizes, int n_in,
                              void* d_out, int out_size) {
    (void)in_sizes; (void)n_in; (void)out_size;
    const float* x    = (const float*)d_in[0];
    const float* mask = (const float*)d_in[1];
    const float* Wq   = (const float*)d_in[2];
    const float* bq   = (const float*)d_in[3];
    const float* Wk   = (const float*)d_in[4];
    const float* bk   = (const float*)d_in[5];
    const float* Wv   = (const float*)d_in[6];
    const float* bv   = (const float*)d_in[7];
    const float* Wql  = (const float*)d_in[8];
    const float* bql  = (const float*)d_in[9];
    const float* Wkl  = (const float*)d_in[10];
    const float* bkl  = (const float*)d_in[11];
    const float* Wo   = (const float*)d_in[12];
    const float* bo   = (const float*)d_in[13];
    float* out = (float*)d_out;

    float *pWqEff, *pWkEff, *pbqEff, *pbkEff, *pQ, *pK, *pV, *pCtx;
    float *pXr, *pWvr, *pWor;
    cudaGetSymbolAddress((void**)&pWqEff, g_WqEff);
    cudaGetSymbolAddress((void**)&pWkEff, g_WkEff);
    cudaGetSymbolAddress((void**)&pbqEff, g_bqEff);
    cudaGetSymbolAddress((void**)&pbkEff, g_bkEff);
    cudaGetSymbolAddress((void**)&pQ,    g_Qlow);
    cudaGetSymbolAddress((void**)&pK,    g_Klow);
    cudaGetSymbolAddress((void**)&pV,    g_V);
    cudaGetSymbolAddress((void**)&pCtx,  g_ctx);
    cudaGetSymbolAddress((void**)&pXr,   g_xr);
    cudaGetSymbolAddress((void**)&pWvr,  g_Wvr);
    cudaGetSymbolAddress((void**)&pWor,  g_Wor);

    cudaFuncSetAttribute(attn_mma_kernel,
                         cudaFuncAttributeMaxDynamicSharedMemorySize, ATTN_SMEM);

    // pre-round mma inputs to tf32 (RNA)
    round_tf32_kernel<<<(MD*HDIM/4 + 255)/256, 256>>>(x, pXr, MD*HDIM/4);
    round_tf32_kernel<<<(HDIM*HDIM/4 + 255)/256, 256>>>(Wv, pWvr, HDIM*HDIM/4);
    round_tf32_kernel<<<(HDIM*HDIM/4 + 255)/256, 256>>>(Wo, pWor, HDIM*HDIM/4);

    weff_kernel<<<dim3(HDIM / 4, NHD), 256>>>(Wq, Wql, bq, bql, pWqEff, pbqEff);
    weff_kernel<<<dim3(HDIM / 4, NHD), 256>>>(Wk, Wkl, bk, bkl, pWkEff, pbkEff);

    // fused Q/K/V projections (grid.z = 3), outputs rounded to tf32
    gemm_pipe<true><<<dim3(HDIM/128, MD/128, 3), 256>>>(
        pXr, pWqEff, pWkEff, pWvr, pbqEff, pbkEff, bv, pQ, pK, pV);

    attn_mma_kernel<<<dim3(SD / 128, NHD, BD), 256, ATTN_SMEM>>>(mask);

    // output projection (exact fp32 epilogue)
    gemm_pipe<false><<<dim3(HDIM/128, MD/128, 1), 256>>>(
        pCtx, pWor, pWor, pWor, bo, bo, bo, out, out, out);
}

// round 14
// speedup vs baseline: 8.7409x; 1.9220x over previous
#include <cuda_runtime.h>
#include <cuda_fp16.h>
#include <math.h>
#include <stdint.h>

#define BD 2
#define SD 2048
#define HDIM 1024
#define NHD 16
#define HDD 64
#define RD 64
#define MD (BD*SD)   /* 4096 */

static __device__ __forceinline__ float4 ldf4(const float* p) {
    return *reinterpret_cast<const float4*>(p);
}
static __device__ __forceinline__ uint32_t h2pk(float a, float b) {
    __half2 h = __floats2half2_rn(a, b);
    return *reinterpret_cast<uint32_t*>(&h);
}
// m16n8k16 fp16 mma, fp32 accumulate (sm_80+ PTX, valid on compute_103)
static __device__ __forceinline__ void mma_f16(float* d, const uint32_t* a,
                                               const uint32_t* b) {
    asm volatile(
        "mma.sync.aligned.m16n8k16.row.col.f32.f16.f16.f32 "
        "{%0,%1,%2,%3}, {%4,%5,%6,%7}, {%8,%9}, {%0,%1,%2,%3};"
        : "+f"(d[0]), "+f"(d[1]), "+f"(d[2]), "+f"(d[3])
        : "r"(a[0]), "r"(a[1]), "r"(a[2]), "r"(a[3]), "r"(b[0]), "r"(b[1]));
}
static __device__ __forceinline__ uint32_t smem_u32(const void* p) {
    uint32_t a;
    asm("{ .reg .u64 t; cvta.to.shared.u64 t, %1; cvt.u32.u64 %0, t; }"
        : "=r"(a) : "l"(p));
    return a;
}
static __device__ __forceinline__ void cp16(uint32_t dst, const void* src) {
    asm volatile("cp.async.cg.shared.global [%0], [%1], 16;"
                 :: "r"(dst), "l"(src) : "memory");
}
#define CP_COMMIT() asm volatile("cp.async.commit_group;" ::: "memory")
#define CP_WAIT1()  asm volatile("cp.async.wait_group 1;" ::: "memory")
#define CP_WAIT0()  asm volatile("cp.async.wait_group 0;" ::: "memory")

// ---------------- scratch (device globals; no allocation allowed) ----------
__device__ __half g_xh  [(size_t)MD*HDIM];
__device__ __half g_Wqt [HDIM*HDIM];    // WqEff^T [n][k]
__device__ __half g_Wkt [HDIM*HDIM];
__device__ __half g_Wvt [HDIM*HDIM];    // Wv^T
__device__ __half g_Wot [HDIM*HDIM];    // Wo^T
__device__ float  g_bqEff[HDIM];
__device__ float  g_bkEff[HDIM];
__device__ __half g_Qh  [(size_t)MD*HDIM];
__device__ __half g_Kh  [(size_t)MD*HDIM];
__device__ __half g_Vh  [(size_t)MD*HDIM];
__device__ __half g_ctxh[(size_t)MD*HDIM];

// ---------------------------------------------------------------------------
// x (fp32) -> half
// ---------------------------------------------------------------------------
__global__ void cvt_half_kernel(const float* __restrict__ in,
                                __half* __restrict__ out, int n8) {
    int i = blockIdx.x * 256 + threadIdx.x;
    if (i < n8) {
        float4 a = ldf4(in + (size_t)i * 8);
        float4 b = ldf4(in + (size_t)i * 8 + 4);
        uint4 o = make_uint4(h2pk(a.x, a.y), h2pk(a.z, a.w),
                             h2pk(b.x, b.y), h2pk(b.z, b.w));
        *reinterpret_cast<uint4*>(out + (size_t)i * 8) = o;
    }
}

// ---------------------------------------------------------------------------
// W[k][n] fp32 -> Wt[n][k] half  (64x64 tiles via smem)
// ---------------------------------------------------------------------------
__global__ void transpose_half_kernel(const float* __restrict__ W,
                                      __half* __restrict__ Wt) {
    __shared__ float ts[64 * 68];
    const int n0 = blockIdx.x * 64, k0 = blockIdx.y * 64;
    const int t = threadIdx.x;
    #pragma unroll
    for (int p = 0; p < 4; p++) {
        const int row = (t >> 4) + p * 16;        // k-local
        const int col = (t & 15) * 4;             // n-local
        *reinterpret_cast<float4*>(&ts[row * 68 + col]) =
            ldf4(W + (size_t)(k0 + row) * HDIM + n0 + col);
    }
    __syncthreads();
    const int nl = t >> 2, c0 = (t & 3) * 16;
    uint32_t o[8];
    #pragma unroll
    for (int j = 0; j < 8; j++)
        o[j] = h2pk(ts[(c0 + 2*j) * 68 + nl], ts[(c0 + 2*j + 1) * 68 + nl]);
    __half* dst = Wt + (size_t)(n0 + nl) * HDIM + k0 + c0;
    *reinterpret_cast<uint4*>(dst)     = make_uint4(o[0], o[1], o[2], o[3]);
    *reinterpret_cast<uint4*>(dst + 8) = make_uint4(o[4], o[5], o[6], o[7]);
}

// ---------------------------------------------------------------------------
// Effective low-rank weights, written transposed as half:
// WeffT[h*64+r][k] = sum_d W[k][h*64+d] * Wl[d][r]
// grid (16 kblk, 16 head), block 256.
// ---------------------------------------------------------------------------
__global__ void weff_kernel(const float* __restrict__ W,
                            const float* __restrict__ Wl,
                            const float* __restrict__ b,
                            const float* __restrict__ bl,
                            __half* __restrict__ WeffT,
                            float* __restrict__ beff) {
    __shared__ float Wls[64 * 64];     // Wl[d][r]
    __shared__ float Wtile[64 * 64];   // W[k0+kl][h*64+d]
    const int h = blockIdx.y, k0 = blockIdx.x * 64;
    const int t = threadIdx.x;
    #pragma unroll
    for (int p = 0; p < 4; p++) {
        const int row = (t >> 4) + p * 16, col = (t & 15) * 4;
        *reinterpret_cast<float4*>(&Wls[row * 64 + col]) =
            ldf4(Wl + row * RD + col);
        *reinterpret_cast<float4*>(&Wtile[row * 64 + col]) =
            ldf4(W + (size_t)(k0 + row) * HDIM + h * HDD + col);
    }
    __syncthreads();
    const int r = t & 63, kq = t >> 6;
    uint32_t o[8];
    #pragma unroll
    for (int ip = 0; ip < 8; ip++) {
        float acc0 = 0.f, acc1 = 0.f;
        const int kl0 = kq * 16 + ip * 2;
        #pragma unroll
        for (int d = 0; d < 64; d++) {
            const float wl = Wls[d * 64 + r];
            acc0 += Wtile[kl0 * 64 + d] * wl;
            acc1 += Wtile[(kl0 + 1) * 64 + d] * wl;
        }
        o[ip] = h2pk(acc0, acc1);
    }
    __half* dst = WeffT + (size_t)(h * 64 + r) * HDIM + k0 + kq * 16;
    *reinterpret_cast<uint4*>(dst)     = make_uint4(o[0], o[1], o[2], o[3]);
    *reinterpret_cast<uint4*>(dst + 8) = make_uint4(o[4], o[5], o[6], o[7]);
    if (blockIdx.x == 0 && kq == 0) {
        float bacc = bl[r];
        #pragma unroll
        for (int d = 0; d < 64; d++) bacc += b[h * HDD + d] * Wls[d * 64 + r];
        beff[h * 64 + r] = bacc;
    }
}

// ---------------------------------------------------------------------------
// fp16 GEMM: C[4096,1024] = A[m][k] @ Wt[n][k]^T + bias.
// CTA 128x128, BK=64, cp.async double buffer, 8 warps 4(m)x2(n).
// smem pitch 72 halves (36 words) -> all frag LDS32 conflict-free.
// ---------------------------------------------------------------------------
static constexpr int GPW = 36;                    // words per smem row
static constexpr int G_STAGE_H = 2 * 128 * 72;    // A+B halves per stage
static constexpr int G_SMEM = 2 * G_STAGE_H * 2;  // bytes (73728)

template<bool HOUT>
__global__ __launch_bounds__(256, 2)
void gemm_h(const __half* __restrict__ A,
            const __half* __restrict__ W0, const __half* __restrict__ W1,
            const __half* __restrict__ W2,
            const float* __restrict__ B0, const float* __restrict__ B1,
            const float* __restrict__ B2,
            void* __restrict__ C0, void* __restrict__ C1,
            void* __restrict__ C2) {
    extern __shared__ char dynsm[];
    const __half* W = (blockIdx.z == 0) ? W0 : (blockIdx.z == 1) ? W1 : W2;
    const float* bias = (blockIdx.z == 0) ? B0 : (blockIdx.z == 1) ? B1 : B2;
    void* C = (blockIdx.z == 0) ? C0 : (blockIdx.z == 1) ? C1 : C2;

    const int tid = threadIdx.x;
    const int wid = tid >> 5, lane = tid & 31;
    const int lr = lane >> 2, lc = lane & 3;
    const int warp_m = wid & 3, warp_n = wid >> 2;
    const int m0 = blockIdx.y * 128, n0 = blockIdx.x * 128;

    const uint32_t smb = smem_u32(dynsm);
    const uint32_t* Sw = reinterpret_cast<const uint32_t*>(dynsm);

    auto issue = [&](int c) {
        const int k0 = c * 64, buf = c & 1;
        const uint32_t base = smb + buf * G_STAGE_H * 2;
        #pragma unroll
        for (int it = 0; it < 4; it++) {
            const int cc = it * 256 + tid;
            const int m = cc >> 3, ck = cc & 7;
            cp16(base + (uint32_t)(m * 144 + ck * 16),
                 A + (size_t)(m0 + m) * HDIM + k0 + ck * 8);
        }
        #pragma unroll
        for (int it = 0; it < 4; it++) {
            const int cc = it * 256 + tid;
            const int n = cc >> 3, ck = cc & 7;
            cp16(base + (uint32_t)(128 * 144 + n * 144 + ck * 16),
                 W + (size_t)(n0 + n) * HDIM + k0 + ck * 8);
        }
        CP_COMMIT();
    };

    float acc[2][8][4];
    #pragma unroll
    for (int mt = 0; mt < 2; mt++)
        #pragma unroll
        for (int nt = 0; nt < 8; nt++)
            #pragma unroll
            for (int e = 0; e < 4; e++) acc[mt][nt][e] = 0.f;

    issue(0);
    for (int c = 0; c < 16; c++) {
        if (c < 15) { issue(c + 1); CP_WAIT1(); } else { CP_WAIT0(); }
        __syncthreads();
        const uint32_t* Aw = Sw + (c & 1) * G_STAGE_H / 2;
        const uint32_t* Bw = Aw + 128 * GPW;
        #pragma unroll
        for (int ks = 0; ks < 4; ks++) {
            const int kwo = ks * 8 + lc;
            uint32_t af[2][4], bf[8][2];
            #pragma unroll
            for (int mt = 0; mt < 2; mt++) {
                const int rb = (warp_m * 32 + mt * 16 + lr) * GPW + kwo;
                af[mt][0] = Aw[rb];           af[mt][1] = Aw[rb + 8 * GPW];
                af[mt][2] = Aw[rb + 4];       af[mt][3] = Aw[rb + 8 * GPW + 4];
            }
            #pragma unroll
            for (int nt = 0; nt < 8; nt++) {
                const int nb = (warp_n * 64 + nt * 8 + lr) * GPW + kwo;
                bf[nt][0] = Bw[nb]; bf[nt][1] = Bw[nb + 4];
            }
            #pragma unroll
            for (int mt = 0; mt < 2; mt++)
                #pragma unroll
                for (int nt = 0; nt < 8; nt++)
                    mma_f16(acc[mt][nt], af[mt], bf[nt]);
        }
        __syncthreads();
    }

    #pragma unroll
    for (int mt = 0; mt < 2; mt++) {
        const int r = m0 + warp_m * 32 + mt * 16 + lr;
        #pragma unroll
        for (int nt = 0; nt < 8; nt++) {
            const int cc = n0 + warp_n * 64 + nt * 8 + lc * 2;
            const float b0 = bias[cc], b1 = bias[cc + 1];
            if (HOUT) {
                __half* Ch = (__half*)C;
                *reinterpret_cast<uint32_t*>(Ch + (size_t)r * HDIM + cc) =
                    h2pk(acc[mt][nt][0] + b0, acc[mt][nt][1] + b1);
                *reinterpret_cast<uint32_t*>(Ch + (size_t)(r + 8) * HDIM + cc) =
                    h2pk(acc[mt][nt][2] + b0, acc[mt][nt][3] + b1);
            } else {
                float* Cf = (float*)C;
                *reinterpret_cast<float2*>(Cf + (size_t)r * HDIM + cc) =
                    make_float2(acc[mt][nt][0] + b0, acc[mt][nt][1] + b1);
                *reinterpret_cast<float2*>(Cf + (size_t)(r + 8) * HDIM + cc) =
                    make_float2(acc[mt][nt][2] + b0, acc[mt][nt][3] + b1);
            }
        }
    }
}

// ---------------------------------------------------------------------------
// fp16 tensor-core flash attention.
// CTA: 128 queries, 8 warps (16 rows each), 32 iters of 64 keys.
// smem (halves, pitch 72): Qs[q][r], Ks[key][r], Vt[d][key], Ps[q][key].
// ---------------------------------------------------------------------------
static constexpr int AP72 = 72;
static constexpr int A_QS = 0;
static constexpr int A_KS = 128 * AP72;            // 9216
static constexpr int A_VT = A_KS + 64 * AP72;      // 13824
static constexpr int A_PS = A_VT + 64 * AP72;      // 18432
static constexpr int A_MS = (A_PS + 128 * AP72) * 2;  // byte offset of mask
static constexpr int ATTN_SMEM = A_MS + 64 * 4;
static constexpr float SCALE = 0.125f;

__global__ __launch_bounds__(256)
void attn_h_kernel(const float* __restrict__ mask) {
    extern __shared__ char dynsm[];
    __half* smh = reinterpret_cast<__half*>(dynsm);
    uint32_t* smw = reinterpret_cast<uint32_t*>(dynsm);
    float* ms = reinterpret_cast<float*>(dynsm + A_MS);

    const int b = blockIdx.z, h = blockIdx.y, qt = blockIdx.x;
    const int tid = threadIdx.x;
    const int wid = tid >> 5, lane = tid & 31;
    const int lr = lane >> 2, lc = lane & 3;
    const int row0 = wid * 16 + lr;
    const size_t qbase = (size_t)b * SD + qt * 128;

    // stage Q once
    #pragma unroll
    for (int it = 0; it < 4; it++) {
        const int c = it * 256 + tid;
        const int q = c >> 3, ck = c & 7;
        *reinterpret_cast<uint4*>(&smh[A_QS + q * AP72 + ck * 8]) =
            *reinterpret_cast<const uint4*>(
                &g_Qh[(qbase + q) * HDIM + h * 64 + ck * 8]);
    }

    float Ofr[8][4];
    #pragma unroll
    for (int nt = 0; nt < 8; nt++)
        #pragma unroll
        for (int e = 0; e < 4; e++) Ofr[nt][e] = 0.f;
    float m_[2] = {-1e30f, -1e30f}, l_[2] = {0.f, 0.f};

    const int vkp = (tid & 31) * 2, vdg = tid >> 5;   // V transpose map

    for (int kt = 0; kt < SD / 64; kt++) {
        __syncthreads();
        const size_t kb0 = (size_t)b * SD + kt * 64;
        #pragma unroll
        for (int it = 0; it < 2; it++) {
            const int c = it * 256 + tid;
            const int k = c >> 3, ck = c & 7;
            *reinterpret_cast<uint4*>(&smh[A_KS + k * AP72 + ck * 8]) =
                *reinterpret_cast<const uint4*>(
                    &g_Kh[(kb0 + k) * HDIM + h * 64 + ck * 8]);
        }
        // V: load 2 rows x 8 d, pack key-pairs, store transposed (STS32)
        {
            uint4 v0 = *reinterpret_cast<const uint4*>(
                &g_Vh[(kb0 + vkp) * HDIM + h * 64 + vdg * 8]);
            uint4 v1 = *reinterpret_cast<const uint4*>(
                &g_Vh[(kb0 + vkp + 1) * HDIM + h * 64 + vdg * 8]);
            const __half* h0 = reinterpret_cast<const __half*>(&v0);
            const __half* h1 = reinterpret_cast<const __half*>(&v1);
            #pragma unroll
            for (int j = 0; j < 8; j++) {
                __half2 p = __halves2half2(h0[j], h1[j]);
                smw[(A_VT >> 1) + (vdg * 8 + j) * GPW + (vkp >> 1)] =
                    *reinterpret_cast<uint32_t*>(&p);
            }
        }
        if (tid < 64) ms[tid] = mask[(size_t)b * SD + kt * 64 + tid];
        __syncthreads();

        // ---- S = Q . K^T (4 k-steps of 16) -------------------------------
        float sfr[8][4];
        #pragma unroll
        for (int nt = 0; nt < 8; nt++)
            #pragma unroll
            for (int e = 0; e < 4; e++) sfr[nt][e] = 0.f;

        #pragma unroll
        for (int ks = 0; ks < 4; ks++) {
            const int kwo = ks * 8 + lc;
            uint32_t af[4];
            const int qb = (A_QS >> 1) + row0 * GPW + kwo;
            af[0] = smw[qb];     af[1] = smw[qb + 8 * GPW];
            af[2] = smw[qb + 4]; af[3] = smw[qb + 8 * GPW + 4];
            #pragma unroll
            for (int nt = 0; nt < 8; nt++) {
                const int kb2 = (A_KS >> 1) + (nt * 8 + lr) * GPW + kwo;
                uint32_t bf[2] = {smw[kb2], smw[kb2 + 4]};
                mma_f16(sfr[nt], af, bf);
            }
        }

        // ---- online softmax ----------------------------------------------
        float mv[8][2];
        #pragma unroll
        for (int nt = 0; nt < 8; nt++) {
            float2 mm = *reinterpret_cast<const float2*>(&ms[nt * 8 + 2 * lc]);
            mv[nt][0] = mm.x; mv[nt][1] = mm.y;
        }
        #pragma unroll
        for (int rr = 0; rr < 2; rr++) {
            float rm = -1e30f;
            #pragma unroll
            for (int nt = 0; nt < 8; nt++)
                #pragma unroll
                for (int e = 0; e < 2; e++) {
                    float v = sfr[nt][rr * 2 + e] * SCALE + mv[nt][e];
                    sfr[nt][rr * 2 + e] = v;
                    rm = fmaxf(rm, v);
                }
            rm = fmaxf(rm, __shfl_xor_sync(0xffffffffu, rm, 1));
            rm = fmaxf(rm, __shfl_xor_sync(0xffffffffu, rm, 2));
            const float mn = fmaxf(m_[rr], rm);
            float rs = 0.f;
            #pragma unroll
            for (int nt = 0; nt < 8; nt++)
                #pragma unroll
                for (int e = 0; e < 2; e++) {
                    float p = __expf(sfr[nt][rr * 2 + e] - mn);
                    sfr[nt][rr * 2 + e] = p;
                    rs += p;
                }
            rs += __shfl_xor_sync(0xffffffffu, rs, 1);
            rs += __shfl_xor_sync(0xffffffffu, rs, 2);
            const float f = __expf(m_[rr] - mn);
            l_[rr] = l_[rr] * f + rs;
            m_[rr] = mn;
            #pragma unroll
            for (int nt = 0; nt < 8; nt++) {
                Ofr[nt][rr * 2 + 0] *= f;
                Ofr[nt][rr * 2 + 1] *= f;
            }
        }

        // ---- P -> smem (half) --------------------------------------------
        #pragma unroll
        for (int nt = 0; nt < 8; nt++) {
            const int pw = (A_PS >> 1) + row0 * GPW + nt * 4 + lc;
            smw[pw]            = h2pk(sfr[nt][0], sfr[nt][1]);
            smw[pw + 8 * GPW]  = h2pk(sfr[nt][2], sfr[nt][3]);
        }
        __syncthreads();

        // ---- O += P . V (4 k-steps of 16 keys) ---------------------------
        #pragma unroll
        for (int ks = 0; ks < 4; ks++) {
            const int kwo = ks * 8 + lc;
            uint32_t af[4];
            const int pb = (A_PS >> 1) + row0 * GPW + kwo;
            af[0] = smw[pb];     af[1] = smw[pb + 8 * GPW];
            af[2] = smw[pb + 4]; af[3] = smw[pb + 8 * GPW + 4];
            #pragma unroll
            for (int nt = 0; nt < 8; nt++) {
                const int vb = (A_VT >> 1) + (nt * 8 + lr) * GPW + kwo;
                uint32_t bf[2] = {smw[vb], smw[vb + 4]};
                mma_f16(Ofr[nt], af, bf);
            }
        }
    }

    // epilogue: normalize, write half ctx
    const float inv0 = 1.f / l_[0], inv1 = 1.f / l_[1];
    const size_t rg = (qbase + row0) * HDIM + h * 64;
    #pragma unroll
    for (int nt = 0; nt < 8; nt++) {
        *reinterpret_cast<uint32_t*>(&g_ctxh[rg + nt * 8 + 2 * lc]) =
            h2pk(Ofr[nt][0] * inv0, Ofr[nt][1] * inv0);
        *reinterpret_cast<uint32_t*>(&g_ctxh[rg + 8 * HDIM + nt * 8 + 2 * lc]) =
            h2pk(Ofr[nt][2] * inv1, Ofr[nt][3] * inv1);
    }
}

// ---------------------------------------------------------------------------
extern "C" void kernel_launch(void* const* d_in, const int* in_sizes, int n_in,
                              void* d_out, int out_size) {
    (void)in_sizes; (void)n_in; (void)out_size;
    const float* x    = (const float*)d_in[0];
    const float* mask = (const float*)d_in[1];
    const float* Wq   = (const float*)d_in[2];
    const float* bq   = (const float*)d_in[3];
    const float* Wk   = (const float*)d_in[4];
    const float* bk   = (const float*)d_in[5];
    const float* Wv   = (const float*)d_in[6];
    const float* bv   = (const float*)d_in[7];
    const float* Wql  = (const float*)d_in[8];
    const float* bql  = (const float*)d_in[9];
    const float* Wkl  = (const float*)d_in[10];
    const float* bkl  = (const float*)d_in[11];
    const float* Wo   = (const float*)d_in[12];
    const float* bo   = (const float*)d_in[13];
    float* out = (float*)d_out;

    __half *pXh, *pWqt, *pWkt, *pWvt, *pWot, *pQ, *pK, *pV, *pCtx;
    float *pbq, *pbk;
    cudaGetSymbolAddress((void**)&pXh,  g_xh);
    cudaGetSymbolAddress((void**)&pWqt, g_Wqt);
    cudaGetSymbolAddress((void**)&pWkt, g_Wkt);
    cudaGetSymbolAddress((void**)&pWvt, g_Wvt);
    cudaGetSymbolAddress((void**)&pWot, g_Wot);
    cudaGetSymbolAddress((void**)&pbq,  g_bqEff);
    cudaGetSymbolAddress((void**)&pbk,  g_bkEff);
    cudaGetSymbolAddress((void**)&pQ,   g_Qh);
    cudaGetSymbolAddress((void**)&pK,   g_Kh);
    cudaGetSymbolAddress((void**)&pV,   g_Vh);
    cudaGetSymbolAddress((void**)&pCtx, g_ctxh);

    cudaFuncSetAttribute(gemm_h<true>,
                         cudaFuncAttributeMaxDynamicSharedMemorySize, G_SMEM);
    cudaFuncSetAttribute(gemm_h<false>,
                         cudaFuncAttributeMaxDynamicSharedMemorySize, G_SMEM);
    cudaFuncSetAttribute(attn_h_kernel,
                         cudaFuncAttributeMaxDynamicSharedMemorySize, ATTN_SMEM);

    // pre-pass: halve x, transpose+halve Wv/Wo, build effective weights
    cvt_half_kernel<<<(MD*HDIM/8 + 255)/256, 256>>>(x, pXh, MD*HDIM/8);
    transpose_half_kernel<<<dim3(16, 16), 256>>>(Wv, pWvt);
    transpose_half_kernel<<<dim3(16, 16), 256>>>(Wo, pWot);
    weff_kernel<<<dim3(16, 16), 256>>>(Wq, Wql, bq, bql, pWqt, pbq);
    weff_kernel<<<dim3(16, 16), 256>>>(Wk, Wkl, bk, bkl, pWkt, pbk);

    // fused Q/K/V projections -> half outputs
    gemm_h<true><<<dim3(HDIM/128, MD/128, 3), 256, G_SMEM>>>(
        pXh, pWqt, pWkt, pWvt, pbq, pbk, bv, pQ, pK, pV);

    attn_h_kernel<<<dim3(SD / 128, NHD, BD), 256, ATTN_SMEM>>>(mask);

    // output projection -> fp32 out
    gemm_h<false><<<dim3(HDIM/128, MD/128, 1), 256, G_SMEM>>>(
        pCtx, pWot, pWot, pWot, bo, bo, bo, out, out, out);
}